// round 14
// baseline (speedup 1.0000x reference)
#include <cuda_runtime.h>
#include <cuda_fp16.h>
#include <cstdint>

#define N_NODES 50000
#define N_EDGES 800000
#define HID 128

typedef unsigned long long ull;

// ---------------- device-global scratch (no allocations allowed) ----------------
__device__ float4 g_mi4[N_NODES * (HID / 4)];
__device__ float g_P[N_NODES * HID];          // h @ We1[24:152] + b1  (bias folded)
__device__ float g_Q[N_NODES * HID];          // h @ We1[152:280]
// B fragments (fp16, single-rounded) packed as uint2 {bh0, bh1}
// COALESCED layout: idx = ((nb*KS + ks)*32 + g*4 + q), nb = n>>3
__device__ uint2 g_w1f2[16 * 2 * 32];         // We1[0:24] (K pad 32), KS=2
__device__ uint2 g_w2f2[16 * 8 * 32];         // We2, KS=8
__device__ uint2 g_wpf2[16 * 8 * 32];         // We1[24:152], KS=8
__device__ uint2 g_wqf2[16 * 8 * 32];         // We1[152:280], KS=8
__device__ uint2 g_wn1f2[16 * 16 * 32];       // Wn1 (K=256), KS=16
__device__ uint2 g_wn2f2[16 * 8 * 32];        // Wn2, KS=8

// ---------------- helpers ----------------
// fp16 hi/lo split of an fp32 pair (A operand): a = hi + lo, |lo| <= 2^-11 |a|
__device__ __forceinline__ void split_pack(float v0, float v1, uint32_t& hi, uint32_t& lo) {
    __half2 h2 = __floats2half2_rn(v0, v1);
    float r0 = v0 - __half2float(h2.x);
    float r1 = v1 - __half2float(h2.y);
    __half2 l2 = __floats2half2_rn(r0, r1);
    hi = *reinterpret_cast<uint32_t*>(&h2);
    lo = *reinterpret_cast<uint32_t*>(&l2);
}
// single fp16 pack (B operand)
__device__ __forceinline__ uint32_t pack_h(float v0, float v1) {
    __half2 h2 = __floats2half2_rn(v0, v1);
    return *reinterpret_cast<uint32_t*>(&h2);
}

__device__ __forceinline__ void mma_f16(float* d, const uint32_t* a, const uint32_t* b) {
    asm volatile("mma.sync.aligned.m16n8k16.row.col.f32.f16.f16.f32 "
        "{%0,%1,%2,%3}, {%4,%5,%6,%7}, {%8,%9}, {%0,%1,%2,%3};"
        : "+f"(d[0]), "+f"(d[1]), "+f"(d[2]), "+f"(d[3])
        : "r"(a[0]), "r"(a[1]), "r"(a[2]), "r"(a[3]), "r"(b[0]), "r"(b[1]));
}

__device__ __forceinline__ uint2 make_bfrag(const float* W, int n, int ks, int q,
                                            int kmax, int ldw) {
    int kp0 = ks * 8 + q, kp1 = ks * 8 + 4 + q;
    float a0 = (2 * kp0     < kmax) ? W[(2 * kp0)     * ldw + n] : 0.f;
    float a1 = (2 * kp0 + 1 < kmax) ? W[(2 * kp0 + 1) * ldw + n] : 0.f;
    float b0 = (2 * kp1     < kmax) ? W[(2 * kp1)     * ldw + n] : 0.f;
    float b1 = (2 * kp1 + 1 < kmax) ? W[(2 * kp1 + 1) * ldw + n] : 0.f;
    return make_uint2(pack_h(a0, a1), pack_h(b0, b1));
}

// decompose coalesced index li (for given log2(KS)) -> n, ks, q
__device__ __forceinline__ void decomp(int li, int ksbits, int& n, int& ks, int& q) {
    q = li & 3;
    int g = (li >> 2) & 7;
    int r2 = li >> 5;
    ks = r2 & ((1 << ksbits) - 1);
    int nb = r2 >> ksbits;
    n = nb * 8 + g;
}

// ---------------- merged zero + prep kernel ----------------
__global__ void prep_zero_kernel(const float* __restrict__ W1, const float* __restrict__ W2,
                                 const float* __restrict__ Wn1, const float* __restrict__ Wn2) {
    int i = blockIdx.x * blockDim.x + threadIdx.x;
    if (i < N_NODES * (HID / 4))
        g_mi4[i] = make_float4(0.f, 0.f, 0.f, 0.f);
    if (i < 25600) {
        int n, ks, q;
        if (i < 1024) {
            decomp(i, 1, n, ks, q);
            g_w1f2[i] = make_bfrag(W1, n, ks, q, 24, 128);
        } else if (i < 5120) {
            int li = i - 1024; decomp(li, 3, n, ks, q);
            g_w2f2[li] = make_bfrag(W2, n, ks, q, 128, 128);
        } else if (i < 9216) {
            int li = i - 5120; decomp(li, 3, n, ks, q);
            g_wpf2[li] = make_bfrag(W1 + 24 * 128, n, ks, q, 128, 128);
        } else if (i < 13312) {
            int li = i - 9216; decomp(li, 3, n, ks, q);
            g_wqf2[li] = make_bfrag(W1 + 152 * 128, n, ks, q, 128, 128);
        } else if (i < 21504) {
            int li = i - 13312; decomp(li, 4, n, ks, q);
            g_wn1f2[li] = make_bfrag(Wn1, n, ks, q, 256, 128);
        } else {
            int li = i - 21504; decomp(li, 3, n, ks, q);
            g_wn2f2[li] = make_bfrag(Wn2, n, ks, q, 128, 128);
        }
    }
}

// ---------------- A-tile staging: 64 rows x 128 k, 128 threads ----------------
__device__ __forceinline__ void stage_tile64(const float* __restrict__ src, int n0,
                                             uint4* ahi4, uint4* alo4, int tid) {
    const int rb = tid >> 5, g = (tid >> 2) & 7, q = tid & 3;
    const int r = rb * 16 + g;
    const int gn0 = n0 + r, gn8 = gn0 + 8;
    const bool v0 = gn0 < N_NODES, v8 = gn8 < N_NODES;
    const float2* s0 = (const float2*)src + (size_t)gn0 * 64;
    const float2* s8 = (const float2*)src + (size_t)gn8 * 64;
    const float2 z = make_float2(0.f, 0.f);
#pragma unroll
    for (int ks = 0; ks < 8; ks++) {
        int kp = ks * 8 + q;
        float2 a = v0 ? __ldg(&s0[kp])     : z;
        float2 b = v8 ? __ldg(&s8[kp])     : z;
        float2 c = v0 ? __ldg(&s0[kp + 4]) : z;
        float2 d = v8 ? __ldg(&s8[kp + 4]) : z;
        uint32_t h0, l0, h1, l1, h2, l2, h3, l3;
        split_pack(a.x, a.y, h0, l0);
        split_pack(b.x, b.y, h1, l1);
        split_pack(c.x, c.y, h2, l2);
        split_pack(d.x, d.y, h3, l3);
        int idx = ((rb * 8 + ks) * 8 + g) * 4 + q;
        ahi4[idx] = make_uint4(h0, h1, h2, h3);
        alo4[idx] = make_uint4(l0, l1, l2, l3);
    }
}

// ---------------- pq kernel: 64 nodes / 128 threads / 4 CTAs per SM ----------------
#define SMEM_PQ 32768

extern "C" __global__ void __launch_bounds__(128, 4)
pq_tensor_kernel(const float* __restrict__ h, const float* __restrict__ b1) {
    extern __shared__ __align__(16) uint4 smf[];
    uint4* ahi4 = smf;
    uint4* alo4 = smf + 1024;

    const int tid = threadIdx.x;
    const int wid = tid >> 5, lane = tid & 31;
    const int g = lane >> 2, q = lane & 3;
    const int wm = wid & 1, wn = wid >> 1;
    const int wq4 = g * 4 + q;
    const int n0 = blockIdx.x * 64;

    stage_tile64(h, n0, ahi4, alo4, tid);
    __syncthreads();

#pragma unroll
    for (int pass = 0; pass < 2; pass++) {
        const uint2* wf = (pass == 0) ? g_wpf2 : g_wqf2;
        float* outp = (pass == 0) ? g_P : g_Q;

        float acc[2][8][4];
#pragma unroll
        for (int mt = 0; mt < 2; mt++)
#pragma unroll
            for (int nt = 0; nt < 8; nt++)
#pragma unroll
                for (int x = 0; x < 4; x++) acc[mt][nt][x] = 0.f;

#pragma unroll 2
        for (int ks = 0; ks < 8; ks++) {
            uint32_t Ah[2][4], Al[2][4];
#pragma unroll
            for (int mt = 0; mt < 2; mt++) {
                int rb = wm * 2 + mt;
                int idx = ((rb * 8 + ks) * 8 + g) * 4 + q;
                uint4 vh = ahi4[idx];
                Ah[mt][0] = vh.x; Ah[mt][1] = vh.y; Ah[mt][2] = vh.z; Ah[mt][3] = vh.w;
                uint4 vl = alo4[idx];
                Al[mt][0] = vl.x; Al[mt][1] = vl.y; Al[mt][2] = vl.z; Al[mt][3] = vl.w;
            }
#pragma unroll
            for (int nt = 0; nt < 8; nt++) {
                uint2 w = __ldg(&wf[((wn * 8 + nt) * 8 + ks) * 32 + wq4]);
                uint32_t bh[2] = {w.x, w.y};
#pragma unroll
                for (int mt = 0; mt < 2; mt++) {
                    mma_f16(acc[mt][nt], Ah[mt], bh);
                    mma_f16(acc[mt][nt], Al[mt], bh);
                }
            }
        }

#pragma unroll
        for (int mt = 0; mt < 2; mt++) {
            int r = wm * 32 + mt * 16 + g;
            int gn0 = n0 + r, gn8 = gn0 + 8;
            bool v0 = gn0 < N_NODES, v8 = gn8 < N_NODES;
#pragma unroll
            for (int nt = 0; nt < 8; nt++) {
                int c = wn * 64 + nt * 8 + q * 2;
                float2 bv = (pass == 0) ? __ldg((const float2*)&b1[c]) : make_float2(0.f, 0.f);
                if (v0) *(float2*)&outp[gn0 * 128 + c] =
                    make_float2(acc[mt][nt][0] + bv.x, acc[mt][nt][1] + bv.y);
                if (v8) *(float2*)&outp[gn8 * 128 + c] =
                    make_float2(acc[mt][nt][2] + bv.x, acc[mt][nt][3] + bv.y);
            }
        }
    }
}

// ---------------- node kernel: 64 nodes / 128 threads / 4 CTAs per SM ----------------
#define SMEM_NODE 32768

extern "C" __global__ void __launch_bounds__(128, 4)
node_tensor_kernel(const float* __restrict__ h,
                   const float* __restrict__ bn1, const float* __restrict__ bn2,
                   float* __restrict__ out)
{
    extern __shared__ __align__(16) uint4 smf[];
    uint4* ahi4 = smf;
    uint4* alo4 = smf + 1024;

    const int tid = threadIdx.x;
    const int wid = tid >> 5, lane = tid & 31;
    const int g = lane >> 2, q = lane & 3;
    const int wm = wid & 1, wn = wid >> 1;
    const int wq4 = g * 4 + q;
    const int n0 = blockIdx.x * 64;

    float acc[2][8][4];
#pragma unroll
    for (int mt = 0; mt < 2; mt++)
#pragma unroll
        for (int nt = 0; nt < 8; nt++)
#pragma unroll
            for (int x = 0; x < 4; x++) acc[mt][nt][x] = 0.f;

    // ===== phase 1a: mi part (Wn1 ks 0..7) =====
    stage_tile64((const float*)g_mi4, n0, ahi4, alo4, tid);
    __syncthreads();
#pragma unroll 2
    for (int ks = 0; ks < 8; ks++) {
        uint32_t Ah[2][4], Al[2][4];
#pragma unroll
        for (int mt = 0; mt < 2; mt++) {
            int rb = wm * 2 + mt;
            int idx = ((rb * 8 + ks) * 8 + g) * 4 + q;
            uint4 vh = ahi4[idx];
            Ah[mt][0] = vh.x; Ah[mt][1] = vh.y; Ah[mt][2] = vh.z; Ah[mt][3] = vh.w;
            uint4 vl = alo4[idx];
            Al[mt][0] = vl.x; Al[mt][1] = vl.y; Al[mt][2] = vl.z; Al[mt][3] = vl.w;
        }
#pragma unroll
        for (int nt = 0; nt < 8; nt++) {
            uint2 w = __ldg(&g_wn1f2[((wn * 8 + nt) * 16 + ks) * 32 + wq4]);
            uint32_t bh[2] = {w.x, w.y};
#pragma unroll
            for (int mt = 0; mt < 2; mt++) {
                mma_f16(acc[mt][nt], Ah[mt], bh);
                mma_f16(acc[mt][nt], Al[mt], bh);
            }
        }
    }
    __syncthreads();

    // ===== phase 1b: h part (Wn1 ks 8..15) =====
    stage_tile64(h, n0, ahi4, alo4, tid);
    __syncthreads();
#pragma unroll 2
    for (int ks = 0; ks < 8; ks++) {
        uint32_t Ah[2][4], Al[2][4];
#pragma unroll
        for (int mt = 0; mt < 2; mt++) {
            int rb = wm * 2 + mt;
            int idx = ((rb * 8 + ks) * 8 + g) * 4 + q;
            uint4 vh = ahi4[idx];
            Ah[mt][0] = vh.x; Ah[mt][1] = vh.y; Ah[mt][2] = vh.z; Ah[mt][3] = vh.w;
            uint4 vl = alo4[idx];
            Al[mt][0] = vl.x; Al[mt][1] = vl.y; Al[mt][2] = vl.z; Al[mt][3] = vl.w;
        }
#pragma unroll
        for (int nt = 0; nt < 8; nt++) {
            uint2 w = __ldg(&g_wn1f2[((wn * 8 + nt) * 16 + (ks + 8)) * 32 + wq4]);
            uint32_t bh[2] = {w.x, w.y};
#pragma unroll
            for (int mt = 0; mt < 2; mt++) {
                mma_f16(acc[mt][nt], Ah[mt], bh);
                mma_f16(acc[mt][nt], Al[mt], bh);
            }
        }
    }
    __syncthreads();

    // ===== epilogue 1: + bn1, relu, split -> fragment smem =====
#pragma unroll
    for (int mt = 0; mt < 2; mt++) {
#pragma unroll
        for (int j = 0; j < 4; j++) {
            uint32_t hi[4], lo[4];
#pragma unroll
            for (int u = 0; u < 2; u++) {
                int nt = 2 * j + u;
                int c = wn * 64 + nt * 8 + q * 2;
                float2 b1v = __ldg((const float2*)&bn1[c]);
                float t0 = fmaxf(acc[mt][nt][0] + b1v.x, 0.f);
                float t1 = fmaxf(acc[mt][nt][1] + b1v.y, 0.f);
                split_pack(t0, t1, hi[2 * u], lo[2 * u]);
                float t2 = fmaxf(acc[mt][nt][2] + b1v.x, 0.f);
                float t3 = fmaxf(acc[mt][nt][3] + b1v.y, 0.f);
                split_pack(t2, t3, hi[2 * u + 1], lo[2 * u + 1]);
            }
            int K8 = wn * 4 + j;
            int rb = wm * 2 + mt;
            int idx = ((rb * 8 + K8) * 8 + g) * 4 + q;
            ahi4[idx] = make_uint4(hi[0], hi[1], hi[2], hi[3]);
            alo4[idx] = make_uint4(lo[0], lo[1], lo[2], lo[3]);
        }
    }
    __syncthreads();

    // ===== phase 2: @ Wn2 =====
#pragma unroll
    for (int mt = 0; mt < 2; mt++)
#pragma unroll
        for (int nt = 0; nt < 8; nt++)
#pragma unroll
            for (int x = 0; x < 4; x++) acc[mt][nt][x] = 0.f;

#pragma unroll 2
    for (int ks = 0; ks < 8; ks++) {
        uint32_t Ah[2][4], Al[2][4];
#pragma unroll
        for (int mt = 0; mt < 2; mt++) {
            int rb = wm * 2 + mt;
            int idx = ((rb * 8 + ks) * 8 + g) * 4 + q;
            uint4 vh = ahi4[idx];
            Ah[mt][0] = vh.x; Ah[mt][1] = vh.y; Ah[mt][2] = vh.z; Ah[mt][3] = vh.w;
            uint4 vl = alo4[idx];
            Al[mt][0] = vl.x; Al[mt][1] = vl.y; Al[mt][2] = vl.z; Al[mt][3] = vl.w;
        }
#pragma unroll
        for (int nt = 0; nt < 8; nt++) {
            uint2 w = __ldg(&g_wn2f2[((wn * 8 + nt) * 8 + ks) * 32 + wq4]);
            uint32_t bh[2] = {w.x, w.y};
#pragma unroll
            for (int mt = 0; mt < 2; mt++) {
                mma_f16(acc[mt][nt], Ah[mt], bh);
                mma_f16(acc[mt][nt], Al[mt], bh);
            }
        }
    }

    // ===== epilogue 2: + bn2 -> out =====
#pragma unroll
    for (int mt = 0; mt < 2; mt++) {
        int r = wm * 32 + mt * 16 + g;
        int gn0 = n0 + r, gn8 = gn0 + 8;
        bool v0 = gn0 < N_NODES, v8 = gn8 < N_NODES;
#pragma unroll
        for (int nt = 0; nt < 8; nt++) {
            int c = wn * 64 + nt * 8 + q * 2;
            float2 b2v = __ldg((const float2*)&bn2[c]);
            if (v0) *(float2*)&out[gn0 * 128 + c] =
                make_float2(acc[mt][nt][0] + b2v.x, acc[mt][nt][1] + b2v.y);
            if (v8) *(float2*)&out[gn8 * 128 + c] =
                make_float2(acc[mt][nt][2] + b2v.x, acc[mt][nt][3] + b2v.y);
        }
    }
}

// ---------------- edge kernel: 64 edges / 128 threads / 4 warps, 5 CTAs per SM ----------------
// smem: a2hi 16KB @0 (eas 6KB overlay), a2lo 16KB @16384,
//       dsts @32768, srcs @33024, gsm @33280 ; total 33536
#define SMEM_EDGE 33536

extern "C" __global__ void __launch_bounds__(128, 5)
edge_kernel(const int* __restrict__ ei, const float* __restrict__ ea,
            const float* __restrict__ b2,
            const float* __restrict__ Wg, const float* __restrict__ bg)
{
    extern __shared__ __align__(16) char sm[];
    uint4* a2hi4 = (uint4*)sm;
    uint4* a2lo4 = (uint4*)(sm + 16384);
    float* eas   = (float*)sm;            // overlay, phase-1 only
    int*   dsts  = (int*)(sm + 32768);
    int*   srcs  = (int*)(sm + 33024);
    float* gsm   = (float*)(sm + 33280);

    const int tid = threadIdx.x;
    const int wid = tid >> 5, lane = tid & 31;
    const int g = lane >> 2, q = lane & 3;
    const int wm = wid & 1, wn = wid >> 1;     // 2 m-groups (M64) x 2 n-groups (N128)
    const int wq4 = g * 4 + q;
    const int e0 = blockIdx.x * 64;

    if (tid < 64) {
        dsts[tid] = ei[e0 + tid];
        srcs[tid] = ei[N_EDGES + e0 + tid];
        gsm[tid] = 0.f;
    }
    {
        const float4* ea4 = (const float4*)ea;
        for (int i = tid; i < 64 * 6; i += 128) {
            int e = i / 6, j = i % 6;
            *(float4*)&eas[e * 24 + j * 4] = ea4[(e0 + e) * 6 + j];
        }
    }
    __syncthreads();

    float acc[2][8][4];
#pragma unroll
    for (int mt = 0; mt < 2; mt++)
#pragma unroll
        for (int nt = 0; nt < 8; nt++)
#pragma unroll
            for (int x = 0; x < 4; x++) acc[mt][nt][x] = 0.f;

    // ===== phase 1: ea @ W1a (K=24 padded to 32) =====
#pragma unroll
    for (int ks = 0; ks < 2; ks++) {
        uint32_t Ah[2][4], Al[2][4];
#pragma unroll
        for (int mt = 0; mt < 2; mt++) {
            int r = wm * 32 + mt * 16 + g;
            int k0 = ks * 16 + q * 2;
            int k8 = k0 + 8;
            float2 v0 = *(const float2*)&eas[r * 24 + k0];
            split_pack(v0.x, v0.y, Ah[mt][0], Al[mt][0]);
            float2 v1 = *(const float2*)&eas[(r + 8) * 24 + k0];
            split_pack(v1.x, v1.y, Ah[mt][1], Al[mt][1]);
            float2 v2 = (k8 < 24) ? *(const float2*)&eas[r * 24 + k8] : make_float2(0.f, 0.f);
            split_pack(v2.x, v2.y, Ah[mt][2], Al[mt][2]);
            float2 v3 = (k8 < 24) ? *(const float2*)&eas[(r + 8) * 24 + k8] : make_float2(0.f, 0.f);
            split_pack(v3.x, v3.y, Ah[mt][3], Al[mt][3]);
        }
#pragma unroll
        for (int nt = 0; nt < 8; nt++) {
            uint2 w = __ldg(&g_w1f2[((wn * 8 + nt) * 2 + ks) * 32 + wq4]);
            uint32_t bh[2] = {w.x, w.y};
#pragma unroll
            for (int mt = 0; mt < 2; mt++) {
                mma_f16(acc[mt][nt], Ah[mt], bh);
                mma_f16(acc[mt][nt], Al[mt], bh);
            }
        }
    }
    __syncthreads();

    // ===== epilogue 1: + (P+b1)[dst] + Q[src], relu, split -> a2 =====
#pragma unroll
    for (int mt = 0; mt < 2; mt++) {
        int r = wm * 32 + mt * 16 + g;
        int d0 = dsts[r], s0 = srcs[r];
        int d8 = dsts[r + 8], s8 = srcs[r + 8];
#pragma unroll
        for (int j = 0; j < 4; j++) {
            uint32_t hi[4], lo[4];
#pragma unroll
            for (int u = 0; u < 2; u++) {
                int nt = 2 * j + u;
                int c = wn * 64 + nt * 8 + q * 2;
                float2 pv0 = __ldg((const float2*)&g_P[d0 * 128 + c]);
                float2 qv0 = __ldg((const float2*)&g_Q[s0 * 128 + c]);
                float t0 = fmaxf(acc[mt][nt][0] + pv0.x + qv0.x, 0.f);
                float t1 = fmaxf(acc[mt][nt][1] + pv0.y + qv0.y, 0.f);
                split_pack(t0, t1, hi[2 * u], lo[2 * u]);
                float2 pv8 = __ldg((const float2*)&g_P[d8 * 128 + c]);
                float2 qv8 = __ldg((const float2*)&g_Q[s8 * 128 + c]);
                float t2 = fmaxf(acc[mt][nt][2] + pv8.x + qv8.x, 0.f);
                float t3 = fmaxf(acc[mt][nt][3] + pv8.y + qv8.y, 0.f);
                split_pack(t2, t3, hi[2 * u + 1], lo[2 * u + 1]);
            }
            int K8 = wn * 4 + j;
            int rb = wm * 2 + mt;               // row block 0..3 over M64
            int idx = ((rb * 8 + K8) * 8 + g) * 4 + q;
            a2hi4[idx] = make_uint4(hi[0], hi[1], hi[2], hi[3]);
            a2lo4[idx] = make_uint4(lo[0], lo[1], lo[2], lo[3]);
        }
    }
    __syncthreads();

    // ===== phase 2: layer2 =====
#pragma unroll
    for (int mt = 0; mt < 2; mt++)
#pragma unroll
        for (int nt = 0; nt < 8; nt++)
#pragma unroll
            for (int x = 0; x < 4; x++) acc[mt][nt][x] = 0.f;

#pragma unroll 2
    for (int ks = 0; ks < 8; ks++) {
        uint32_t Ah[2][4], Al[2][4];
#pragma unroll
        for (int mt = 0; mt < 2; mt++) {
            int rb = wm * 2 + mt;
            int idx = ((rb * 8 + ks) * 8 + g) * 4 + q;
            uint4 vh = a2hi4[idx];
            Ah[mt][0] = vh.x; Ah[mt][1] = vh.y; Ah[mt][2] = vh.z; Ah[mt][3] = vh.w;
            uint4 vl = a2lo4[idx];
            Al[mt][0] = vl.x; Al[mt][1] = vl.y; Al[mt][2] = vl.z; Al[mt][3] = vl.w;
        }
#pragma unroll
        for (int nt = 0; nt < 8; nt++) {
            uint2 w = __ldg(&g_w2f2[((wn * 8 + nt) * 8 + ks) * 32 + wq4]);
            uint32_t bh[2] = {w.x, w.y};
#pragma unroll
            for (int mt = 0; mt < 2; mt++) {
                mma_f16(acc[mt][nt], Ah[mt], bh);
                mma_f16(acc[mt][nt], Al[mt], bh);
            }
        }
    }

    // ===== epilogue 2: bias + relu -> m (regs); gate partials =====
    {
        float gp[2][2] = {{0.f, 0.f}, {0.f, 0.f}};
#pragma unroll
        for (int mt = 0; mt < 2; mt++)
#pragma unroll
        for (int nt = 0; nt < 8; nt++) {
            int c = wn * 64 + nt * 8 + q * 2;
            float2 b2v = __ldg((const float2*)&b2[c]);
            float2 wgv = __ldg((const float2*)&Wg[c]);
            float m0 = fmaxf(acc[mt][nt][0] + b2v.x, 0.f);
            float m1 = fmaxf(acc[mt][nt][1] + b2v.y, 0.f);
            float m2 = fmaxf(acc[mt][nt][2] + b2v.x, 0.f);
            float m3 = fmaxf(acc[mt][nt][3] + b2v.y, 0.f);
            gp[mt][0] += m0 * wgv.x + m1 * wgv.y;
            gp[mt][1] += m2 * wgv.x + m3 * wgv.y;
            acc[mt][nt][0] = m0; acc[mt][nt][1] = m1;
            acc[mt][nt][2] = m2; acc[mt][nt][3] = m3;
        }
#pragma unroll
        for (int mt = 0; mt < 2; mt++) {
            atomicAdd(&gsm[wm * 32 + mt * 16 + g],     gp[mt][0]);
            atomicAdd(&gsm[wm * 32 + mt * 16 + g + 8], gp[mt][1]);
        }
    }
    __syncthreads();
    if (tid < 64) gsm[tid] = 1.f / (1.f + expf(-(gsm[tid] + __ldg(bg))));
    __syncthreads();

    // ===== scatter: mi[dst] += m * g =====
    {
        float* g_mif = (float*)g_mi4;
#pragma unroll
        for (int mt = 0; mt < 2; mt++) {
            int r = wm * 32 + mt * 16 + g;
            float gg0 = gsm[r], gg1 = gsm[r + 8];
            int d0 = dsts[r], d8 = dsts[r + 8];
#pragma unroll
            for (int nt = 0; nt < 8; nt++) {
                int c = wn * 64 + nt * 8 + q * 2;
                atomicAdd((float2*)&g_mif[d0 * 128 + c],
                          make_float2(acc[mt][nt][0] * gg0, acc[mt][nt][1] * gg0));
                atomicAdd((float2*)&g_mif[d8 * 128 + c],
                          make_float2(acc[mt][nt][2] * gg1, acc[mt][nt][3] * gg1));
            }
        }
    }
}

// ---------------- launch ----------------
extern "C" void kernel_launch(void* const* d_in, const int* in_sizes, int n_in,
                              void* d_out, int out_size)
{
    const float* h   = (const float*)d_in[0];
    const int*   ei  = (const int*)d_in[1];
    const float* ea  = (const float*)d_in[2];
    const float* We1 = (const float*)d_in[3];
    const float* b1  = (const float*)d_in[4];
    const float* We2 = (const float*)d_in[5];
    const float* b2  = (const float*)d_in[6];
    const float* Wg  = (const float*)d_in[7];
    const float* bg  = (const float*)d_in[8];
    const float* Wn1 = (const float*)d_in[9];
    const float* bn1 = (const float*)d_in[10];
    const float* Wn2 = (const float*)d_in[11];
    const float* bn2 = (const float*)d_in[12];
    float* out = (float*)d_out;

    cudaFuncSetAttribute(edge_kernel, cudaFuncAttributeMaxDynamicSharedMemorySize, SMEM_EDGE);
    cudaFuncSetAttribute(pq_tensor_kernel, cudaFuncAttributeMaxDynamicSharedMemorySize, SMEM_PQ);
    cudaFuncSetAttribute(node_tensor_kernel, cudaFuncAttributeMaxDynamicSharedMemorySize, SMEM_NODE);

    const int nblk = (N_NODES + 63) / 64;     // 782
    prep_zero_kernel<<<(N_NODES * (HID / 4) + 511) / 512, 512>>>(We1, We2, Wn1, Wn2);
    pq_tensor_kernel<<<nblk, 128, SMEM_PQ>>>(h, b1);
    edge_kernel<<<N_EDGES / 64, 128, SMEM_EDGE>>>(ei, ea, b2, Wg, bg);
    node_tensor_kernel<<<nblk, 128, SMEM_NODE>>>(h, bn1, bn2, out);
}

// round 15
// speedup vs baseline: 1.2128x; 1.2128x over previous
#include <cuda_runtime.h>
#include <cuda_fp16.h>
#include <cstdint>

#define N_NODES 50000
#define N_EDGES 800000
#define HID 128

typedef unsigned long long ull;

// ---------------- device-global scratch (no allocations allowed) ----------------
__device__ float4 g_mi4[N_NODES * (HID / 4)];
__device__ float g_P[N_NODES * HID];          // h @ We1[24:152] + b1  (bias folded)
__device__ float g_Q[N_NODES * HID];          // h @ We1[152:280]
// B fragments (fp16, single-rounded) packed as uint2 {bh0, bh1}
// COALESCED layout: idx = ((nb*KS + ks)*32 + g*4 + q), nb = n>>3
__device__ uint2 g_w1f2[16 * 2 * 32];         // We1[0:24] (K pad 32), KS=2
__device__ uint2 g_w2f2[16 * 8 * 32];         // We2, KS=8
__device__ uint2 g_wpf2[16 * 8 * 32];         // We1[24:152], KS=8
__device__ uint2 g_wqf2[16 * 8 * 32];         // We1[152:280], KS=8
__device__ uint2 g_wn1f2[16 * 16 * 32];       // Wn1 (K=256), KS=16
__device__ uint2 g_wn2f2[16 * 8 * 32];        // Wn2, KS=8

// ---------------- helpers ----------------
// fp16 hi/lo split of an fp32 pair (A operand): a = hi + lo, |lo| <= 2^-11 |a|
__device__ __forceinline__ void split_pack(float v0, float v1, uint32_t& hi, uint32_t& lo) {
    __half2 h2 = __floats2half2_rn(v0, v1);
    float r0 = v0 - __half2float(h2.x);
    float r1 = v1 - __half2float(h2.y);
    __half2 l2 = __floats2half2_rn(r0, r1);
    hi = *reinterpret_cast<uint32_t*>(&h2);
    lo = *reinterpret_cast<uint32_t*>(&l2);
}
// single fp16 pack (B operand)
__device__ __forceinline__ uint32_t pack_h(float v0, float v1) {
    __half2 h2 = __floats2half2_rn(v0, v1);
    return *reinterpret_cast<uint32_t*>(&h2);
}

__device__ __forceinline__ void mma_f16(float* d, const uint32_t* a, const uint32_t* b) {
    asm volatile("mma.sync.aligned.m16n8k16.row.col.f32.f16.f16.f32 "
        "{%0,%1,%2,%3}, {%4,%5,%6,%7}, {%8,%9}, {%0,%1,%2,%3};"
        : "+f"(d[0]), "+f"(d[1]), "+f"(d[2]), "+f"(d[3])
        : "r"(a[0]), "r"(a[1]), "r"(a[2]), "r"(a[3]), "r"(b[0]), "r"(b[1]));
}

__device__ __forceinline__ uint2 make_bfrag(const float* W, int n, int ks, int q,
                                            int kmax, int ldw) {
    int kp0 = ks * 8 + q, kp1 = ks * 8 + 4 + q;
    float a0 = (2 * kp0     < kmax) ? W[(2 * kp0)     * ldw + n] : 0.f;
    float a1 = (2 * kp0 + 1 < kmax) ? W[(2 * kp0 + 1) * ldw + n] : 0.f;
    float b0 = (2 * kp1     < kmax) ? W[(2 * kp1)     * ldw + n] : 0.f;
    float b1 = (2 * kp1 + 1 < kmax) ? W[(2 * kp1 + 1) * ldw + n] : 0.f;
    return make_uint2(pack_h(a0, a1), pack_h(b0, b1));
}

// decompose coalesced index li (for given log2(KS)) -> n, ks, q
__device__ __forceinline__ void decomp(int li, int ksbits, int& n, int& ks, int& q) {
    q = li & 3;
    int g = (li >> 2) & 7;
    int r2 = li >> 5;
    ks = r2 & ((1 << ksbits) - 1);
    int nb = r2 >> ksbits;
    n = nb * 8 + g;
}

// ---------------- merged zero + prep kernel ----------------
__global__ void prep_zero_kernel(const float* __restrict__ W1, const float* __restrict__ W2,
                                 const float* __restrict__ Wn1, const float* __restrict__ Wn2) {
    int i = blockIdx.x * blockDim.x + threadIdx.x;
    if (i < N_NODES * (HID / 4))
        g_mi4[i] = make_float4(0.f, 0.f, 0.f, 0.f);
    if (i < 25600) {
        int n, ks, q;
        if (i < 1024) {
            decomp(i, 1, n, ks, q);
            g_w1f2[i] = make_bfrag(W1, n, ks, q, 24, 128);
        } else if (i < 5120) {
            int li = i - 1024; decomp(li, 3, n, ks, q);
            g_w2f2[li] = make_bfrag(W2, n, ks, q, 128, 128);
        } else if (i < 9216) {
            int li = i - 5120; decomp(li, 3, n, ks, q);
            g_wpf2[li] = make_bfrag(W1 + 24 * 128, n, ks, q, 128, 128);
        } else if (i < 13312) {
            int li = i - 9216; decomp(li, 3, n, ks, q);
            g_wqf2[li] = make_bfrag(W1 + 152 * 128, n, ks, q, 128, 128);
        } else if (i < 21504) {
            int li = i - 13312; decomp(li, 4, n, ks, q);
            g_wn1f2[li] = make_bfrag(Wn1, n, ks, q, 256, 128);
        } else {
            int li = i - 21504; decomp(li, 3, n, ks, q);
            g_wn2f2[li] = make_bfrag(Wn2, n, ks, q, 128, 128);
        }
    }
}

// ---------------- A-tile staging: 64 rows x 128 k, 128 threads ----------------
__device__ __forceinline__ void stage_tile64(const float* __restrict__ src, int n0,
                                             uint4* ahi4, uint4* alo4, int tid) {
    const int rb = tid >> 5, g = (tid >> 2) & 7, q = tid & 3;
    const int r = rb * 16 + g;
    const int gn0 = n0 + r, gn8 = gn0 + 8;
    const bool v0 = gn0 < N_NODES, v8 = gn8 < N_NODES;
    const float2* s0 = (const float2*)src + (size_t)gn0 * 64;
    const float2* s8 = (const float2*)src + (size_t)gn8 * 64;
    const float2 z = make_float2(0.f, 0.f);
#pragma unroll
    for (int ks = 0; ks < 8; ks++) {
        int kp = ks * 8 + q;
        float2 a = v0 ? __ldg(&s0[kp])     : z;
        float2 b = v8 ? __ldg(&s8[kp])     : z;
        float2 c = v0 ? __ldg(&s0[kp + 4]) : z;
        float2 d = v8 ? __ldg(&s8[kp + 4]) : z;
        uint32_t h0, l0, h1, l1, h2, l2, h3, l3;
        split_pack(a.x, a.y, h0, l0);
        split_pack(b.x, b.y, h1, l1);
        split_pack(c.x, c.y, h2, l2);
        split_pack(d.x, d.y, h3, l3);
        int idx = ((rb * 8 + ks) * 8 + g) * 4 + q;
        ahi4[idx] = make_uint4(h0, h1, h2, h3);
        alo4[idx] = make_uint4(l0, l1, l2, l3);
    }
}

// ---------------- pq kernel: 64 nodes / 128 threads / 4 CTAs per SM ----------------
#define SMEM_PQ 32768

extern "C" __global__ void __launch_bounds__(128, 4)
pq_tensor_kernel(const float* __restrict__ h, const float* __restrict__ b1) {
    extern __shared__ __align__(16) uint4 smf[];
    uint4* ahi4 = smf;
    uint4* alo4 = smf + 1024;

    const int tid = threadIdx.x;
    const int wid = tid >> 5, lane = tid & 31;
    const int g = lane >> 2, q = lane & 3;
    const int wm = wid & 1, wn = wid >> 1;
    const int wq4 = g * 4 + q;
    const int n0 = blockIdx.x * 64;

    stage_tile64(h, n0, ahi4, alo4, tid);
    __syncthreads();

#pragma unroll
    for (int pass = 0; pass < 2; pass++) {
        const uint2* wf = (pass == 0) ? g_wpf2 : g_wqf2;
        float* outp = (pass == 0) ? g_P : g_Q;

        float acc[2][8][4];
#pragma unroll
        for (int mt = 0; mt < 2; mt++)
#pragma unroll
            for (int nt = 0; nt < 8; nt++)
#pragma unroll
                for (int x = 0; x < 4; x++) acc[mt][nt][x] = 0.f;

#pragma unroll 2
        for (int ks = 0; ks < 8; ks++) {
            uint32_t Ah[2][4], Al[2][4];
#pragma unroll
            for (int mt = 0; mt < 2; mt++) {
                int rb = wm * 2 + mt;
                int idx = ((rb * 8 + ks) * 8 + g) * 4 + q;
                uint4 vh = ahi4[idx];
                Ah[mt][0] = vh.x; Ah[mt][1] = vh.y; Ah[mt][2] = vh.z; Ah[mt][3] = vh.w;
                uint4 vl = alo4[idx];
                Al[mt][0] = vl.x; Al[mt][1] = vl.y; Al[mt][2] = vl.z; Al[mt][3] = vl.w;
            }
#pragma unroll
            for (int nt = 0; nt < 8; nt++) {
                uint2 w = __ldg(&wf[((wn * 8 + nt) * 8 + ks) * 32 + wq4]);
                uint32_t bh[2] = {w.x, w.y};
#pragma unroll
                for (int mt = 0; mt < 2; mt++) {
                    mma_f16(acc[mt][nt], Ah[mt], bh);
                    mma_f16(acc[mt][nt], Al[mt], bh);
                }
            }
        }

#pragma unroll
        for (int mt = 0; mt < 2; mt++) {
            int r = wm * 32 + mt * 16 + g;
            int gn0 = n0 + r, gn8 = gn0 + 8;
            bool v0 = gn0 < N_NODES, v8 = gn8 < N_NODES;
#pragma unroll
            for (int nt = 0; nt < 8; nt++) {
                int c = wn * 64 + nt * 8 + q * 2;
                float2 bv = (pass == 0) ? __ldg((const float2*)&b1[c]) : make_float2(0.f, 0.f);
                if (v0) *(float2*)&outp[gn0 * 128 + c] =
                    make_float2(acc[mt][nt][0] + bv.x, acc[mt][nt][1] + bv.y);
                if (v8) *(float2*)&outp[gn8 * 128 + c] =
                    make_float2(acc[mt][nt][2] + bv.x, acc[mt][nt][3] + bv.y);
            }
        }
    }
}

// ---------------- node kernel: 64 nodes / 128 threads / 4 CTAs per SM ----------------
#define SMEM_NODE 32768

extern "C" __global__ void __launch_bounds__(128, 4)
node_tensor_kernel(const float* __restrict__ h,
                   const float* __restrict__ bn1, const float* __restrict__ bn2,
                   float* __restrict__ out)
{
    extern __shared__ __align__(16) uint4 smf[];
    uint4* ahi4 = smf;
    uint4* alo4 = smf + 1024;

    const int tid = threadIdx.x;
    const int wid = tid >> 5, lane = tid & 31;
    const int g = lane >> 2, q = lane & 3;
    const int wm = wid & 1, wn = wid >> 1;
    const int wq4 = g * 4 + q;
    const int n0 = blockIdx.x * 64;

    float acc[2][8][4];
#pragma unroll
    for (int mt = 0; mt < 2; mt++)
#pragma unroll
        for (int nt = 0; nt < 8; nt++)
#pragma unroll
            for (int x = 0; x < 4; x++) acc[mt][nt][x] = 0.f;

    // ===== phase 1a: mi part (Wn1 ks 0..7) =====
    stage_tile64((const float*)g_mi4, n0, ahi4, alo4, tid);
    __syncthreads();
#pragma unroll 2
    for (int ks = 0; ks < 8; ks++) {
        uint32_t Ah[2][4], Al[2][4];
#pragma unroll
        for (int mt = 0; mt < 2; mt++) {
            int rb = wm * 2 + mt;
            int idx = ((rb * 8 + ks) * 8 + g) * 4 + q;
            uint4 vh = ahi4[idx];
            Ah[mt][0] = vh.x; Ah[mt][1] = vh.y; Ah[mt][2] = vh.z; Ah[mt][3] = vh.w;
            uint4 vl = alo4[idx];
            Al[mt][0] = vl.x; Al[mt][1] = vl.y; Al[mt][2] = vl.z; Al[mt][3] = vl.w;
        }
#pragma unroll
        for (int nt = 0; nt < 8; nt++) {
            uint2 w = __ldg(&g_wn1f2[((wn * 8 + nt) * 16 + ks) * 32 + wq4]);
            uint32_t bh[2] = {w.x, w.y};
#pragma unroll
            for (int mt = 0; mt < 2; mt++) {
                mma_f16(acc[mt][nt], Ah[mt], bh);
                mma_f16(acc[mt][nt], Al[mt], bh);
            }
        }
    }
    __syncthreads();

    // ===== phase 1b: h part (Wn1 ks 8..15) =====
    stage_tile64(h, n0, ahi4, alo4, tid);
    __syncthreads();
#pragma unroll 2
    for (int ks = 0; ks < 8; ks++) {
        uint32_t Ah[2][4], Al[2][4];
#pragma unroll
        for (int mt = 0; mt < 2; mt++) {
            int rb = wm * 2 + mt;
            int idx = ((rb * 8 + ks) * 8 + g) * 4 + q;
            uint4 vh = ahi4[idx];
            Ah[mt][0] = vh.x; Ah[mt][1] = vh.y; Ah[mt][2] = vh.z; Ah[mt][3] = vh.w;
            uint4 vl = alo4[idx];
            Al[mt][0] = vl.x; Al[mt][1] = vl.y; Al[mt][2] = vl.z; Al[mt][3] = vl.w;
        }
#pragma unroll
        for (int nt = 0; nt < 8; nt++) {
            uint2 w = __ldg(&g_wn1f2[((wn * 8 + nt) * 16 + (ks + 8)) * 32 + wq4]);
            uint32_t bh[2] = {w.x, w.y};
#pragma unroll
            for (int mt = 0; mt < 2; mt++) {
                mma_f16(acc[mt][nt], Ah[mt], bh);
                mma_f16(acc[mt][nt], Al[mt], bh);
            }
        }
    }
    __syncthreads();

    // ===== epilogue 1: + bn1, relu, split -> fragment smem =====
#pragma unroll
    for (int mt = 0; mt < 2; mt++) {
#pragma unroll
        for (int j = 0; j < 4; j++) {
            uint32_t hi[4], lo[4];
#pragma unroll
            for (int u = 0; u < 2; u++) {
                int nt = 2 * j + u;
                int c = wn * 64 + nt * 8 + q * 2;
                float2 b1v = __ldg((const float2*)&bn1[c]);
                float t0 = fmaxf(acc[mt][nt][0] + b1v.x, 0.f);
                float t1 = fmaxf(acc[mt][nt][1] + b1v.y, 0.f);
                split_pack(t0, t1, hi[2 * u], lo[2 * u]);
                float t2 = fmaxf(acc[mt][nt][2] + b1v.x, 0.f);
                float t3 = fmaxf(acc[mt][nt][3] + b1v.y, 0.f);
                split_pack(t2, t3, hi[2 * u + 1], lo[2 * u + 1]);
            }
            int K8 = wn * 4 + j;
            int rb = wm * 2 + mt;
            int idx = ((rb * 8 + K8) * 8 + g) * 4 + q;
            ahi4[idx] = make_uint4(hi[0], hi[1], hi[2], hi[3]);
            alo4[idx] = make_uint4(lo[0], lo[1], lo[2], lo[3]);
        }
    }
    __syncthreads();

    // ===== phase 2: @ Wn2 =====
#pragma unroll
    for (int mt = 0; mt < 2; mt++)
#pragma unroll
        for (int nt = 0; nt < 8; nt++)
#pragma unroll
            for (int x = 0; x < 4; x++) acc[mt][nt][x] = 0.f;

#pragma unroll 2
    for (int ks = 0; ks < 8; ks++) {
        uint32_t Ah[2][4], Al[2][4];
#pragma unroll
        for (int mt = 0; mt < 2; mt++) {
            int rb = wm * 2 + mt;
            int idx = ((rb * 8 + ks) * 8 + g) * 4 + q;
            uint4 vh = ahi4[idx];
            Ah[mt][0] = vh.x; Ah[mt][1] = vh.y; Ah[mt][2] = vh.z; Ah[mt][3] = vh.w;
            uint4 vl = alo4[idx];
            Al[mt][0] = vl.x; Al[mt][1] = vl.y; Al[mt][2] = vl.z; Al[mt][3] = vl.w;
        }
#pragma unroll
        for (int nt = 0; nt < 8; nt++) {
            uint2 w = __ldg(&g_wn2f2[((wn * 8 + nt) * 8 + ks) * 32 + wq4]);
            uint32_t bh[2] = {w.x, w.y};
#pragma unroll
            for (int mt = 0; mt < 2; mt++) {
                mma_f16(acc[mt][nt], Ah[mt], bh);
                mma_f16(acc[mt][nt], Al[mt], bh);
            }
        }
    }

    // ===== epilogue 2: + bn2 -> out =====
#pragma unroll
    for (int mt = 0; mt < 2; mt++) {
        int r = wm * 32 + mt * 16 + g;
        int gn0 = n0 + r, gn8 = gn0 + 8;
        bool v0 = gn0 < N_NODES, v8 = gn8 < N_NODES;
#pragma unroll
        for (int nt = 0; nt < 8; nt++) {
            int c = wn * 64 + nt * 8 + q * 2;
            float2 b2v = __ldg((const float2*)&bn2[c]);
            if (v0) *(float2*)&out[gn0 * 128 + c] =
                make_float2(acc[mt][nt][0] + b2v.x, acc[mt][nt][1] + b2v.y);
            if (v8) *(float2*)&out[gn8 * 128 + c] =
                make_float2(acc[mt][nt][2] + b2v.x, acc[mt][nt][3] + b2v.y);
        }
    }
}

// ---------------- edge kernel: 64 edges / 128 threads / 4 warps, 4 CTAs per SM ----------------
// smem: a2hi 16KB @0 (eas 6KB overlay), a2lo 16KB @16384,
//       dsts @32768, srcs @33024, gsm @33280 ; total 33536
#define SMEM_EDGE 33536

extern "C" __global__ void __launch_bounds__(128, 4)
edge_kernel(const int* __restrict__ ei, const float* __restrict__ ea,
            const float* __restrict__ b2,
            const float* __restrict__ Wg, const float* __restrict__ bg)
{
    extern __shared__ __align__(16) char sm[];
    uint4* a2hi4 = (uint4*)sm;
    uint4* a2lo4 = (uint4*)(sm + 16384);
    float* eas   = (float*)sm;            // overlay, phase-1 only
    int*   dsts  = (int*)(sm + 32768);
    int*   srcs  = (int*)(sm + 33024);
    float* gsm   = (float*)(sm + 33280);

    const int tid = threadIdx.x;
    const int wid = tid >> 5, lane = tid & 31;
    const int g = lane >> 2, q = lane & 3;
    const int wm = wid & 1, wn = wid >> 1;     // 2 m-groups (M64) x 2 n-groups (N128)
    const int wq4 = g * 4 + q;
    const int e0 = blockIdx.x * 64;

    if (tid < 64) {
        dsts[tid] = ei[e0 + tid];
        srcs[tid] = ei[N_EDGES + e0 + tid];
        gsm[tid] = 0.f;
    }
    {
        const float4* ea4 = (const float4*)ea;
        for (int i = tid; i < 64 * 6; i += 128) {
            int e = i / 6, j = i % 6;
            *(float4*)&eas[e * 24 + j * 4] = ea4[(e0 + e) * 6 + j];
        }
    }
    __syncthreads();

    float acc[2][8][4];
#pragma unroll
    for (int mt = 0; mt < 2; mt++)
#pragma unroll
        for (int nt = 0; nt < 8; nt++)
#pragma unroll
            for (int x = 0; x < 4; x++) acc[mt][nt][x] = 0.f;

    // ===== phase 1: ea @ W1a (K=24 padded to 32) =====
#pragma unroll
    for (int ks = 0; ks < 2; ks++) {
        uint32_t Ah[2][4], Al[2][4];
#pragma unroll
        for (int mt = 0; mt < 2; mt++) {
            int r = wm * 32 + mt * 16 + g;
            int k0 = ks * 16 + q * 2;
            int k8 = k0 + 8;
            float2 v0 = *(const float2*)&eas[r * 24 + k0];
            split_pack(v0.x, v0.y, Ah[mt][0], Al[mt][0]);
            float2 v1 = *(const float2*)&eas[(r + 8) * 24 + k0];
            split_pack(v1.x, v1.y, Ah[mt][1], Al[mt][1]);
            float2 v2 = (k8 < 24) ? *(const float2*)&eas[r * 24 + k8] : make_float2(0.f, 0.f);
            split_pack(v2.x, v2.y, Ah[mt][2], Al[mt][2]);
            float2 v3 = (k8 < 24) ? *(const float2*)&eas[(r + 8) * 24 + k8] : make_float2(0.f, 0.f);
            split_pack(v3.x, v3.y, Ah[mt][3], Al[mt][3]);
        }
#pragma unroll
        for (int nt = 0; nt < 8; nt++) {
            uint2 w = __ldg(&g_w1f2[((wn * 8 + nt) * 2 + ks) * 32 + wq4]);
            uint32_t bh[2] = {w.x, w.y};
#pragma unroll
            for (int mt = 0; mt < 2; mt++) {
                mma_f16(acc[mt][nt], Ah[mt], bh);
                mma_f16(acc[mt][nt], Al[mt], bh);
            }
        }
    }
    __syncthreads();

    // ===== epilogue 1: + (P+b1)[dst] + Q[src], relu, split -> a2 =====
#pragma unroll
    for (int mt = 0; mt < 2; mt++) {
        int r = wm * 32 + mt * 16 + g;
        int d0 = dsts[r], s0 = srcs[r];
        int d8 = dsts[r + 8], s8 = srcs[r + 8];
#pragma unroll
        for (int j = 0; j < 4; j++) {
            uint32_t hi[4], lo[4];
#pragma unroll
            for (int u = 0; u < 2; u++) {
                int nt = 2 * j + u;
                int c = wn * 64 + nt * 8 + q * 2;
                float2 pv0 = __ldg((const float2*)&g_P[d0 * 128 + c]);
                float2 qv0 = __ldg((const float2*)&g_Q[s0 * 128 + c]);
                float t0 = fmaxf(acc[mt][nt][0] + pv0.x + qv0.x, 0.f);
                float t1 = fmaxf(acc[mt][nt][1] + pv0.y + qv0.y, 0.f);
                split_pack(t0, t1, hi[2 * u], lo[2 * u]);
                float2 pv8 = __ldg((const float2*)&g_P[d8 * 128 + c]);
                float2 qv8 = __ldg((const float2*)&g_Q[s8 * 128 + c]);
                float t2 = fmaxf(acc[mt][nt][2] + pv8.x + qv8.x, 0.f);
                float t3 = fmaxf(acc[mt][nt][3] + pv8.y + qv8.y, 0.f);
                split_pack(t2, t3, hi[2 * u + 1], lo[2 * u + 1]);
            }
            int K8 = wn * 4 + j;
            int rb = wm * 2 + mt;               // row block 0..3 over M64
            int idx = ((rb * 8 + K8) * 8 + g) * 4 + q;
            a2hi4[idx] = make_uint4(hi[0], hi[1], hi[2], hi[3]);
            a2lo4[idx] = make_uint4(lo[0], lo[1], lo[2], lo[3]);
        }
    }
    __syncthreads();

    // ===== phase 2: layer2 =====
#pragma unroll
    for (int mt = 0; mt < 2; mt++)
#pragma unroll
        for (int nt = 0; nt < 8; nt++)
#pragma unroll
            for (int x = 0; x < 4; x++) acc[mt][nt][x] = 0.f;

#pragma unroll 2
    for (int ks = 0; ks < 8; ks++) {
        uint32_t Ah[2][4], Al[2][4];
#pragma unroll
        for (int mt = 0; mt < 2; mt++) {
            int rb = wm * 2 + mt;
            int idx = ((rb * 8 + ks) * 8 + g) * 4 + q;
            uint4 vh = a2hi4[idx];
            Ah[mt][0] = vh.x; Ah[mt][1] = vh.y; Ah[mt][2] = vh.z; Ah[mt][3] = vh.w;
            uint4 vl = a2lo4[idx];
            Al[mt][0] = vl.x; Al[mt][1] = vl.y; Al[mt][2] = vl.z; Al[mt][3] = vl.w;
        }
#pragma unroll
        for (int nt = 0; nt < 8; nt++) {
            uint2 w = __ldg(&g_w2f2[((wn * 8 + nt) * 8 + ks) * 32 + wq4]);
            uint32_t bh[2] = {w.x, w.y};
#pragma unroll
            for (int mt = 0; mt < 2; mt++) {
                mma_f16(acc[mt][nt], Ah[mt], bh);
                mma_f16(acc[mt][nt], Al[mt], bh);
            }
        }
    }

    // ===== epilogue 2: bias + relu -> m (regs); gate partials =====
    {
        float gp[2][2] = {{0.f, 0.f}, {0.f, 0.f}};
#pragma unroll
        for (int mt = 0; mt < 2; mt++)
#pragma unroll
        for (int nt = 0; nt < 8; nt++) {
            int c = wn * 64 + nt * 8 + q * 2;
            float2 b2v = __ldg((const float2*)&b2[c]);
            float2 wgv = __ldg((const float2*)&Wg[c]);
            float m0 = fmaxf(acc[mt][nt][0] + b2v.x, 0.f);
            float m1 = fmaxf(acc[mt][nt][1] + b2v.y, 0.f);
            float m2 = fmaxf(acc[mt][nt][2] + b2v.x, 0.f);
            float m3 = fmaxf(acc[mt][nt][3] + b2v.y, 0.f);
            gp[mt][0] += m0 * wgv.x + m1 * wgv.y;
            gp[mt][1] += m2 * wgv.x + m3 * wgv.y;
            acc[mt][nt][0] = m0; acc[mt][nt][1] = m1;
            acc[mt][nt][2] = m2; acc[mt][nt][3] = m3;
        }
#pragma unroll
        for (int mt = 0; mt < 2; mt++) {
            atomicAdd(&gsm[wm * 32 + mt * 16 + g],     gp[mt][0]);
            atomicAdd(&gsm[wm * 32 + mt * 16 + g + 8], gp[mt][1]);
        }
    }
    __syncthreads();
    if (tid < 64) gsm[tid] = 1.f / (1.f + expf(-(gsm[tid] + __ldg(bg))));
    __syncthreads();

    // ===== scatter: mi[dst] += m * g =====
    {
        float* g_mif = (float*)g_mi4;
#pragma unroll
        for (int mt = 0; mt < 2; mt++) {
            int r = wm * 32 + mt * 16 + g;
            float gg0 = gsm[r], gg1 = gsm[r + 8];
            int d0 = dsts[r], d8 = dsts[r + 8];
#pragma unroll
            for (int nt = 0; nt < 8; nt++) {
                int c = wn * 64 + nt * 8 + q * 2;
                atomicAdd((float2*)&g_mif[d0 * 128 + c],
                          make_float2(acc[mt][nt][0] * gg0, acc[mt][nt][1] * gg0));
                atomicAdd((float2*)&g_mif[d8 * 128 + c],
                          make_float2(acc[mt][nt][2] * gg1, acc[mt][nt][3] * gg1));
            }
        }
    }
}

// ---------------- launch ----------------
extern "C" void kernel_launch(void* const* d_in, const int* in_sizes, int n_in,
                              void* d_out, int out_size)
{
    const float* h   = (const float*)d_in[0];
    const int*   ei  = (const int*)d_in[1];
    const float* ea  = (const float*)d_in[2];
    const float* We1 = (const float*)d_in[3];
    const float* b1  = (const float*)d_in[4];
    const float* We2 = (const float*)d_in[5];
    const float* b2  = (const float*)d_in[6];
    const float* Wg  = (const float*)d_in[7];
    const float* bg  = (const float*)d_in[8];
    const float* Wn1 = (const float*)d_in[9];
    const float* bn1 = (const float*)d_in[10];
    const float* Wn2 = (const float*)d_in[11];
    const float* bn2 = (const float*)d_in[12];
    float* out = (float*)d_out;

    cudaFuncSetAttribute(edge_kernel, cudaFuncAttributeMaxDynamicSharedMemorySize, SMEM_EDGE);
    cudaFuncSetAttribute(pq_tensor_kernel, cudaFuncAttributeMaxDynamicSharedMemorySize, SMEM_PQ);
    cudaFuncSetAttribute(node_tensor_kernel, cudaFuncAttributeMaxDynamicSharedMemorySize, SMEM_NODE);

    const int nblk = (N_NODES + 63) / 64;     // 782
    prep_zero_kernel<<<(N_NODES * (HID / 4) + 511) / 512, 512>>>(We1, We2, Wn1, Wn2);
    pq_tensor_kernel<<<nblk, 128, SMEM_PQ>>>(h, b1);
    edge_kernel<<<N_EDGES / 64, 128, SMEM_EDGE>>>(ei, ea, b2, Wg, bg);
    node_tensor_kernel<<<nblk, 128, SMEM_NODE>>>(h, bn1, bn2, out);
}

// round 16
// speedup vs baseline: 1.2200x; 1.0060x over previous
#include <cuda_runtime.h>
#include <cuda_fp16.h>
#include <cstdint>

#define N_NODES 50000
#define N_EDGES 800000
#define HID 128

typedef unsigned long long ull;

// ---------------- device-global scratch (no allocations allowed) ----------------
__device__ float4 g_mi4[N_NODES * (HID / 4)];
__device__ float g_P[N_NODES * HID];          // h @ We1[24:152] + b1  (bias folded)
__device__ float g_Q[N_NODES * HID];          // h @ We1[152:280]
// B fragments (fp16, single-rounded) packed as uint2 {bh0, bh1}
// COALESCED layout: idx = ((nb*KS + ks)*32 + g*4 + q), nb = n>>3
__device__ uint2 g_w1f2[16 * 2 * 32];         // We1[0:24] (K pad 32), KS=2
__device__ uint2 g_w2f2[16 * 8 * 32];         // We2, KS=8
__device__ uint2 g_wpf2[16 * 8 * 32];         // We1[24:152], KS=8
__device__ uint2 g_wqf2[16 * 8 * 32];         // We1[152:280], KS=8
__device__ uint2 g_wn1f2[16 * 16 * 32];       // Wn1 (K=256), KS=16
__device__ uint2 g_wn2f2[16 * 8 * 32];        // Wn2, KS=8

// ---------------- helpers ----------------
// fp16 hi/lo split of an fp32 pair (A operand): a = hi + lo, |lo| <= 2^-11 |a|
__device__ __forceinline__ void split_pack(float v0, float v1, uint32_t& hi, uint32_t& lo) {
    __half2 h2 = __floats2half2_rn(v0, v1);
    float r0 = v0 - __half2float(h2.x);
    float r1 = v1 - __half2float(h2.y);
    __half2 l2 = __floats2half2_rn(r0, r1);
    hi = *reinterpret_cast<uint32_t*>(&h2);
    lo = *reinterpret_cast<uint32_t*>(&l2);
}
// single fp16 pack (B operand)
__device__ __forceinline__ uint32_t pack_h(float v0, float v1) {
    __half2 h2 = __floats2half2_rn(v0, v1);
    return *reinterpret_cast<uint32_t*>(&h2);
}

__device__ __forceinline__ void mma_f16(float* d, const uint32_t* a, const uint32_t* b) {
    asm volatile("mma.sync.aligned.m16n8k16.row.col.f32.f16.f16.f32 "
        "{%0,%1,%2,%3}, {%4,%5,%6,%7}, {%8,%9}, {%0,%1,%2,%3};"
        : "+f"(d[0]), "+f"(d[1]), "+f"(d[2]), "+f"(d[3])
        : "r"(a[0]), "r"(a[1]), "r"(a[2]), "r"(a[3]), "r"(b[0]), "r"(b[1]));
}

// k8 variant: A = {a0 (rows r, k0..7), a1 (rows r+8)}, B = single reg
__device__ __forceinline__ void mma_f16_k8(float* d, uint32_t a0, uint32_t a1, uint32_t b) {
    asm volatile("mma.sync.aligned.m16n8k8.row.col.f32.f16.f16.f32 "
        "{%0,%1,%2,%3}, {%4,%5}, {%6}, {%0,%1,%2,%3};"
        : "+f"(d[0]), "+f"(d[1]), "+f"(d[2]), "+f"(d[3])
        : "r"(a0), "r"(a1), "r"(b));
}

__device__ __forceinline__ uint2 make_bfrag(const float* W, int n, int ks, int q,
                                            int kmax, int ldw) {
    int kp0 = ks * 8 + q, kp1 = ks * 8 + 4 + q;
    float a0 = (2 * kp0     < kmax) ? W[(2 * kp0)     * ldw + n] : 0.f;
    float a1 = (2 * kp0 + 1 < kmax) ? W[(2 * kp0 + 1) * ldw + n] : 0.f;
    float b0 = (2 * kp1     < kmax) ? W[(2 * kp1)     * ldw + n] : 0.f;
    float b1 = (2 * kp1 + 1 < kmax) ? W[(2 * kp1 + 1) * ldw + n] : 0.f;
    return make_uint2(pack_h(a0, a1), pack_h(b0, b1));
}

// decompose coalesced index li (for given log2(KS)) -> n, ks, q
__device__ __forceinline__ void decomp(int li, int ksbits, int& n, int& ks, int& q) {
    q = li & 3;
    int g = (li >> 2) & 7;
    int r2 = li >> 5;
    ks = r2 & ((1 << ksbits) - 1);
    int nb = r2 >> ksbits;
    n = nb * 8 + g;
}

// ---------------- merged zero + prep kernel ----------------
__global__ void prep_zero_kernel(const float* __restrict__ W1, const float* __restrict__ W2,
                                 const float* __restrict__ Wn1, const float* __restrict__ Wn2) {
    int i = blockIdx.x * blockDim.x + threadIdx.x;
    if (i < N_NODES * (HID / 4))
        g_mi4[i] = make_float4(0.f, 0.f, 0.f, 0.f);
    if (i < 25600) {
        int n, ks, q;
        if (i < 1024) {
            decomp(i, 1, n, ks, q);
            g_w1f2[i] = make_bfrag(W1, n, ks, q, 24, 128);
        } else if (i < 5120) {
            int li = i - 1024; decomp(li, 3, n, ks, q);
            g_w2f2[li] = make_bfrag(W2, n, ks, q, 128, 128);
        } else if (i < 9216) {
            int li = i - 5120; decomp(li, 3, n, ks, q);
            g_wpf2[li] = make_bfrag(W1 + 24 * 128, n, ks, q, 128, 128);
        } else if (i < 13312) {
            int li = i - 9216; decomp(li, 3, n, ks, q);
            g_wqf2[li] = make_bfrag(W1 + 152 * 128, n, ks, q, 128, 128);
        } else if (i < 21504) {
            int li = i - 13312; decomp(li, 4, n, ks, q);
            g_wn1f2[li] = make_bfrag(Wn1, n, ks, q, 256, 128);
        } else {
            int li = i - 21504; decomp(li, 3, n, ks, q);
            g_wn2f2[li] = make_bfrag(Wn2, n, ks, q, 128, 128);
        }
    }
}

// ---------------- A-tile staging: 64 rows x 128 k, 128 threads ----------------
__device__ __forceinline__ void stage_tile64(const float* __restrict__ src, int n0,
                                             uint4* ahi4, uint4* alo4, int tid) {
    const int rb = tid >> 5, g = (tid >> 2) & 7, q = tid & 3;
    const int r = rb * 16 + g;
    const int gn0 = n0 + r, gn8 = gn0 + 8;
    const bool v0 = gn0 < N_NODES, v8 = gn8 < N_NODES;
    const float2* s0 = (const float2*)src + (size_t)gn0 * 64;
    const float2* s8 = (const float2*)src + (size_t)gn8 * 64;
    const float2 z = make_float2(0.f, 0.f);
#pragma unroll
    for (int ks = 0; ks < 8; ks++) {
        int kp = ks * 8 + q;
        float2 a = v0 ? __ldg(&s0[kp])     : z;
        float2 b = v8 ? __ldg(&s8[kp])     : z;
        float2 c = v0 ? __ldg(&s0[kp + 4]) : z;
        float2 d = v8 ? __ldg(&s8[kp + 4]) : z;
        uint32_t h0, l0, h1, l1, h2, l2, h3, l3;
        split_pack(a.x, a.y, h0, l0);
        split_pack(b.x, b.y, h1, l1);
        split_pack(c.x, c.y, h2, l2);
        split_pack(d.x, d.y, h3, l3);
        int idx = ((rb * 8 + ks) * 8 + g) * 4 + q;
        ahi4[idx] = make_uint4(h0, h1, h2, h3);
        alo4[idx] = make_uint4(l0, l1, l2, l3);
    }
}

// ---------------- pq kernel: 64 nodes / 128 threads / 4 CTAs per SM ----------------
#define SMEM_PQ 32768

extern "C" __global__ void __launch_bounds__(128, 4)
pq_tensor_kernel(const float* __restrict__ h, const float* __restrict__ b1) {
    extern __shared__ __align__(16) uint4 smf[];
    uint4* ahi4 = smf;
    uint4* alo4 = smf + 1024;

    const int tid = threadIdx.x;
    const int wid = tid >> 5, lane = tid & 31;
    const int g = lane >> 2, q = lane & 3;
    const int wm = wid & 1, wn = wid >> 1;
    const int wq4 = g * 4 + q;
    const int n0 = blockIdx.x * 64;

    stage_tile64(h, n0, ahi4, alo4, tid);
    __syncthreads();

#pragma unroll
    for (int pass = 0; pass < 2; pass++) {
        const uint2* wf = (pass == 0) ? g_wpf2 : g_wqf2;
        float* outp = (pass == 0) ? g_P : g_Q;

        float acc[2][8][4];
#pragma unroll
        for (int mt = 0; mt < 2; mt++)
#pragma unroll
            for (int nt = 0; nt < 8; nt++)
#pragma unroll
                for (int x = 0; x < 4; x++) acc[mt][nt][x] = 0.f;

#pragma unroll 2
        for (int ks = 0; ks < 8; ks++) {
            uint32_t Ah[2][4], Al[2][4];
#pragma unroll
            for (int mt = 0; mt < 2; mt++) {
                int rb = wm * 2 + mt;
                int idx = ((rb * 8 + ks) * 8 + g) * 4 + q;
                uint4 vh = ahi4[idx];
                Ah[mt][0] = vh.x; Ah[mt][1] = vh.y; Ah[mt][2] = vh.z; Ah[mt][3] = vh.w;
                uint4 vl = alo4[idx];
                Al[mt][0] = vl.x; Al[mt][1] = vl.y; Al[mt][2] = vl.z; Al[mt][3] = vl.w;
            }
#pragma unroll
            for (int nt = 0; nt < 8; nt++) {
                uint2 w = __ldg(&wf[((wn * 8 + nt) * 8 + ks) * 32 + wq4]);
                uint32_t bh[2] = {w.x, w.y};
#pragma unroll
                for (int mt = 0; mt < 2; mt++) {
                    mma_f16(acc[mt][nt], Ah[mt], bh);
                    mma_f16(acc[mt][nt], Al[mt], bh);
                }
            }
        }

#pragma unroll
        for (int mt = 0; mt < 2; mt++) {
            int r = wm * 32 + mt * 16 + g;
            int gn0 = n0 + r, gn8 = gn0 + 8;
            bool v0 = gn0 < N_NODES, v8 = gn8 < N_NODES;
#pragma unroll
            for (int nt = 0; nt < 8; nt++) {
                int c = wn * 64 + nt * 8 + q * 2;
                float2 bv = (pass == 0) ? __ldg((const float2*)&b1[c]) : make_float2(0.f, 0.f);
                if (v0) *(float2*)&outp[gn0 * 128 + c] =
                    make_float2(acc[mt][nt][0] + bv.x, acc[mt][nt][1] + bv.y);
                if (v8) *(float2*)&outp[gn8 * 128 + c] =
                    make_float2(acc[mt][nt][2] + bv.x, acc[mt][nt][3] + bv.y);
            }
        }
    }
}

// ---------------- node kernel: 64 nodes / 128 threads / 4 CTAs per SM ----------------
#define SMEM_NODE 32768

extern "C" __global__ void __launch_bounds__(128, 4)
node_tensor_kernel(const float* __restrict__ h,
                   const float* __restrict__ bn1, const float* __restrict__ bn2,
                   float* __restrict__ out)
{
    extern __shared__ __align__(16) uint4 smf[];
    uint4* ahi4 = smf;
    uint4* alo4 = smf + 1024;

    const int tid = threadIdx.x;
    const int wid = tid >> 5, lane = tid & 31;
    const int g = lane >> 2, q = lane & 3;
    const int wm = wid & 1, wn = wid >> 1;
    const int wq4 = g * 4 + q;
    const int n0 = blockIdx.x * 64;

    float acc[2][8][4];
#pragma unroll
    for (int mt = 0; mt < 2; mt++)
#pragma unroll
        for (int nt = 0; nt < 8; nt++)
#pragma unroll
            for (int x = 0; x < 4; x++) acc[mt][nt][x] = 0.f;

    // ===== phase 1a: mi part (Wn1 ks 0..7) =====
    stage_tile64((const float*)g_mi4, n0, ahi4, alo4, tid);
    __syncthreads();
#pragma unroll 2
    for (int ks = 0; ks < 8; ks++) {
        uint32_t Ah[2][4], Al[2][4];
#pragma unroll
        for (int mt = 0; mt < 2; mt++) {
            int rb = wm * 2 + mt;
            int idx = ((rb * 8 + ks) * 8 + g) * 4 + q;
            uint4 vh = ahi4[idx];
            Ah[mt][0] = vh.x; Ah[mt][1] = vh.y; Ah[mt][2] = vh.z; Ah[mt][3] = vh.w;
            uint4 vl = alo4[idx];
            Al[mt][0] = vl.x; Al[mt][1] = vl.y; Al[mt][2] = vl.z; Al[mt][3] = vl.w;
        }
#pragma unroll
        for (int nt = 0; nt < 8; nt++) {
            uint2 w = __ldg(&g_wn1f2[((wn * 8 + nt) * 16 + ks) * 32 + wq4]);
            uint32_t bh[2] = {w.x, w.y};
#pragma unroll
            for (int mt = 0; mt < 2; mt++) {
                mma_f16(acc[mt][nt], Ah[mt], bh);
                mma_f16(acc[mt][nt], Al[mt], bh);
            }
        }
    }
    __syncthreads();

    // ===== phase 1b: h part (Wn1 ks 8..15) =====
    stage_tile64(h, n0, ahi4, alo4, tid);
    __syncthreads();
#pragma unroll 2
    for (int ks = 0; ks < 8; ks++) {
        uint32_t Ah[2][4], Al[2][4];
#pragma unroll
        for (int mt = 0; mt < 2; mt++) {
            int rb = wm * 2 + mt;
            int idx = ((rb * 8 + ks) * 8 + g) * 4 + q;
            uint4 vh = ahi4[idx];
            Ah[mt][0] = vh.x; Ah[mt][1] = vh.y; Ah[mt][2] = vh.z; Ah[mt][3] = vh.w;
            uint4 vl = alo4[idx];
            Al[mt][0] = vl.x; Al[mt][1] = vl.y; Al[mt][2] = vl.z; Al[mt][3] = vl.w;
        }
#pragma unroll
        for (int nt = 0; nt < 8; nt++) {
            uint2 w = __ldg(&g_wn1f2[((wn * 8 + nt) * 16 + (ks + 8)) * 32 + wq4]);
            uint32_t bh[2] = {w.x, w.y};
#pragma unroll
            for (int mt = 0; mt < 2; mt++) {
                mma_f16(acc[mt][nt], Ah[mt], bh);
                mma_f16(acc[mt][nt], Al[mt], bh);
            }
        }
    }
    __syncthreads();

    // ===== epilogue 1: + bn1, relu, split -> fragment smem =====
#pragma unroll
    for (int mt = 0; mt < 2; mt++) {
#pragma unroll
        for (int j = 0; j < 4; j++) {
            uint32_t hi[4], lo[4];
#pragma unroll
            for (int u = 0; u < 2; u++) {
                int nt = 2 * j + u;
                int c = wn * 64 + nt * 8 + q * 2;
                float2 b1v = __ldg((const float2*)&bn1[c]);
                float t0 = fmaxf(acc[mt][nt][0] + b1v.x, 0.f);
                float t1 = fmaxf(acc[mt][nt][1] + b1v.y, 0.f);
                split_pack(t0, t1, hi[2 * u], lo[2 * u]);
                float t2 = fmaxf(acc[mt][nt][2] + b1v.x, 0.f);
                float t3 = fmaxf(acc[mt][nt][3] + b1v.y, 0.f);
                split_pack(t2, t3, hi[2 * u + 1], lo[2 * u + 1]);
            }
            int K8 = wn * 4 + j;
            int rb = wm * 2 + mt;
            int idx = ((rb * 8 + K8) * 8 + g) * 4 + q;
            ahi4[idx] = make_uint4(hi[0], hi[1], hi[2], hi[3]);
            alo4[idx] = make_uint4(lo[0], lo[1], lo[2], lo[3]);
        }
    }
    __syncthreads();

    // ===== phase 2: @ Wn2 =====
#pragma unroll
    for (int mt = 0; mt < 2; mt++)
#pragma unroll
        for (int nt = 0; nt < 8; nt++)
#pragma unroll
            for (int x = 0; x < 4; x++) acc[mt][nt][x] = 0.f;

#pragma unroll 2
    for (int ks = 0; ks < 8; ks++) {
        uint32_t Ah[2][4], Al[2][4];
#pragma unroll
        for (int mt = 0; mt < 2; mt++) {
            int rb = wm * 2 + mt;
            int idx = ((rb * 8 + ks) * 8 + g) * 4 + q;
            uint4 vh = ahi4[idx];
            Ah[mt][0] = vh.x; Ah[mt][1] = vh.y; Ah[mt][2] = vh.z; Ah[mt][3] = vh.w;
            uint4 vl = alo4[idx];
            Al[mt][0] = vl.x; Al[mt][1] = vl.y; Al[mt][2] = vl.z; Al[mt][3] = vl.w;
        }
#pragma unroll
        for (int nt = 0; nt < 8; nt++) {
            uint2 w = __ldg(&g_wn2f2[((wn * 8 + nt) * 8 + ks) * 32 + wq4]);
            uint32_t bh[2] = {w.x, w.y};
#pragma unroll
            for (int mt = 0; mt < 2; mt++) {
                mma_f16(acc[mt][nt], Ah[mt], bh);
                mma_f16(acc[mt][nt], Al[mt], bh);
            }
        }
    }

    // ===== epilogue 2: + bn2 -> out =====
#pragma unroll
    for (int mt = 0; mt < 2; mt++) {
        int r = wm * 32 + mt * 16 + g;
        int gn0 = n0 + r, gn8 = gn0 + 8;
        bool v0 = gn0 < N_NODES, v8 = gn8 < N_NODES;
#pragma unroll
        for (int nt = 0; nt < 8; nt++) {
            int c = wn * 64 + nt * 8 + q * 2;
            float2 b2v = __ldg((const float2*)&bn2[c]);
            if (v0) *(float2*)&out[gn0 * 128 + c] =
                make_float2(acc[mt][nt][0] + b2v.x, acc[mt][nt][1] + b2v.y);
            if (v8) *(float2*)&out[gn8 * 128 + c] =
                make_float2(acc[mt][nt][2] + b2v.x, acc[mt][nt][3] + b2v.y);
        }
    }
}

// ---------------- edge kernel: 64 edges / 128 threads / 4 warps, 4 CTAs per SM ----------------
// smem: a2hi 16KB @0 (eas 6KB overlay), a2lo 16KB @16384,
//       dsts @32768, srcs @33024, gsm @33280 ; total 33536
#define SMEM_EDGE 33536

extern "C" __global__ void __launch_bounds__(128, 4)
edge_kernel(const int* __restrict__ ei, const float* __restrict__ ea,
            const float* __restrict__ b2,
            const float* __restrict__ Wg, const float* __restrict__ bg)
{
    extern __shared__ __align__(16) char sm[];
    uint4* a2hi4 = (uint4*)sm;
    uint4* a2lo4 = (uint4*)(sm + 16384);
    float* eas   = (float*)sm;            // overlay, phase-1 only
    int*   dsts  = (int*)(sm + 32768);
    int*   srcs  = (int*)(sm + 33024);
    float* gsm   = (float*)(sm + 33280);

    const int tid = threadIdx.x;
    const int wid = tid >> 5, lane = tid & 31;
    const int g = lane >> 2, q = lane & 3;
    const int wm = wid & 1, wn = wid >> 1;     // 2 m-groups (M64) x 2 n-groups (N128)
    const int wq4 = g * 4 + q;
    const int e0 = blockIdx.x * 64;

    if (tid < 64) {
        dsts[tid] = ei[e0 + tid];
        srcs[tid] = ei[N_EDGES + e0 + tid];
        gsm[tid] = 0.f;
    }
    {
        const float4* ea4 = (const float4*)ea;
        for (int i = tid; i < 64 * 6; i += 128) {
            int e = i / 6, j = i % 6;
            *(float4*)&eas[e * 24 + j * 4] = ea4[(e0 + e) * 6 + j];
        }
    }
    __syncthreads();

    float acc[2][8][4];
#pragma unroll
    for (int mt = 0; mt < 2; mt++)
#pragma unroll
        for (int nt = 0; nt < 8; nt++)
#pragma unroll
            for (int x = 0; x < 4; x++) acc[mt][nt][x] = 0.f;

    // ===== phase 1: ea @ W1a (K=24): ks=0 full k16; ks=1 as k8 (k=24..31 exactly zero) =====
    {
        uint32_t Ah[2][4], Al[2][4];
        // --- ks = 0: k = 0..15 ---
#pragma unroll
        for (int mt = 0; mt < 2; mt++) {
            int r = wm * 32 + mt * 16 + g;
            int k0 = q * 2;
            float2 v0 = *(const float2*)&eas[r * 24 + k0];
            split_pack(v0.x, v0.y, Ah[mt][0], Al[mt][0]);
            float2 v1 = *(const float2*)&eas[(r + 8) * 24 + k0];
            split_pack(v1.x, v1.y, Ah[mt][1], Al[mt][1]);
            float2 v2 = *(const float2*)&eas[r * 24 + k0 + 8];
            split_pack(v2.x, v2.y, Ah[mt][2], Al[mt][2]);
            float2 v3 = *(const float2*)&eas[(r + 8) * 24 + k0 + 8];
            split_pack(v3.x, v3.y, Ah[mt][3], Al[mt][3]);
        }
#pragma unroll
        for (int nt = 0; nt < 8; nt++) {
            uint2 w = __ldg(&g_w1f2[((wn * 8 + nt) * 2 + 0) * 32 + wq4]);
            uint32_t bh[2] = {w.x, w.y};
#pragma unroll
            for (int mt = 0; mt < 2; mt++) {
                mma_f16(acc[mt][nt], Ah[mt], bh);
                mma_f16(acc[mt][nt], Al[mt], bh);
            }
        }
        // --- ks = 1: only k = 16..23 nonzero -> m16n8k8 with fragments 0/1 and b.x ---
#pragma unroll
        for (int mt = 0; mt < 2; mt++) {
            int r = wm * 32 + mt * 16 + g;
            int k0 = 16 + q * 2;
            float2 v0 = *(const float2*)&eas[r * 24 + k0];
            split_pack(v0.x, v0.y, Ah[mt][0], Al[mt][0]);
            float2 v1 = *(const float2*)&eas[(r + 8) * 24 + k0];
            split_pack(v1.x, v1.y, Ah[mt][1], Al[mt][1]);
        }
#pragma unroll
        for (int nt = 0; nt < 8; nt++) {
            uint2 w = __ldg(&g_w1f2[((wn * 8 + nt) * 2 + 1) * 32 + wq4]);
#pragma unroll
            for (int mt = 0; mt < 2; mt++) {
                mma_f16_k8(acc[mt][nt], Ah[mt][0], Ah[mt][1], w.x);
                mma_f16_k8(acc[mt][nt], Al[mt][0], Al[mt][1], w.x);
            }
        }
    }
    __syncthreads();

    // ===== epilogue 1: + (P+b1)[dst] + Q[src], relu, split -> a2 =====
#pragma unroll
    for (int mt = 0; mt < 2; mt++) {
        int r = wm * 32 + mt * 16 + g;
        int d0 = dsts[r], s0 = srcs[r];
        int d8 = dsts[r + 8], s8 = srcs[r + 8];
#pragma unroll
        for (int j = 0; j < 4; j++) {
            uint32_t hi[4], lo[4];
#pragma unroll
            for (int u = 0; u < 2; u++) {
                int nt = 2 * j + u;
                int c = wn * 64 + nt * 8 + q * 2;
                float2 pv0 = __ldg((const float2*)&g_P[d0 * 128 + c]);
                float2 qv0 = __ldg((const float2*)&g_Q[s0 * 128 + c]);
                float t0 = fmaxf(acc[mt][nt][0] + pv0.x + qv0.x, 0.f);
                float t1 = fmaxf(acc[mt][nt][1] + pv0.y + qv0.y, 0.f);
                split_pack(t0, t1, hi[2 * u], lo[2 * u]);
                float2 pv8 = __ldg((const float2*)&g_P[d8 * 128 + c]);
                float2 qv8 = __ldg((const float2*)&g_Q[s8 * 128 + c]);
                float t2 = fmaxf(acc[mt][nt][2] + pv8.x + qv8.x, 0.f);
                float t3 = fmaxf(acc[mt][nt][3] + pv8.y + qv8.y, 0.f);
                split_pack(t2, t3, hi[2 * u + 1], lo[2 * u + 1]);
            }
            int K8 = wn * 4 + j;
            int rb = wm * 2 + mt;               // row block 0..3 over M64
            int idx = ((rb * 8 + K8) * 8 + g) * 4 + q;
            a2hi4[idx] = make_uint4(hi[0], hi[1], hi[2], hi[3]);
            a2lo4[idx] = make_uint4(lo[0], lo[1], lo[2], lo[3]);
        }
    }
    __syncthreads();

    // ===== phase 2: layer2 =====
#pragma unroll
    for (int mt = 0; mt < 2; mt++)
#pragma unroll
        for (int nt = 0; nt < 8; nt++)
#pragma unroll
            for (int x = 0; x < 4; x++) acc[mt][nt][x] = 0.f;

#pragma unroll 2
    for (int ks = 0; ks < 8; ks++) {
        uint32_t Ah[2][4], Al[2][4];
#pragma unroll
        for (int mt = 0; mt < 2; mt++) {
            int rb = wm * 2 + mt;
            int idx = ((rb * 8 + ks) * 8 + g) * 4 + q;
            uint4 vh = a2hi4[idx];
            Ah[mt][0] = vh.x; Ah[mt][1] = vh.y; Ah[mt][2] = vh.z; Ah[mt][3] = vh.w;
            uint4 vl = a2lo4[idx];
            Al[mt][0] = vl.x; Al[mt][1] = vl.y; Al[mt][2] = vl.z; Al[mt][3] = vl.w;
        }
#pragma unroll
        for (int nt = 0; nt < 8; nt++) {
            uint2 w = __ldg(&g_w2f2[((wn * 8 + nt) * 8 + ks) * 32 + wq4]);
            uint32_t bh[2] = {w.x, w.y};
#pragma unroll
            for (int mt = 0; mt < 2; mt++) {
                mma_f16(acc[mt][nt], Ah[mt], bh);
                mma_f16(acc[mt][nt], Al[mt], bh);
            }
        }
    }

    // ===== epilogue 2: bias + relu -> m (regs); gate partials =====
    {
        float gp[2][2] = {{0.f, 0.f}, {0.f, 0.f}};
#pragma unroll
        for (int mt = 0; mt < 2; mt++)
#pragma unroll
        for (int nt = 0; nt < 8; nt++) {
            int c = wn * 64 + nt * 8 + q * 2;
            float2 b2v = __ldg((const float2*)&b2[c]);
            float2 wgv = __ldg((const float2*)&Wg[c]);
            float m0 = fmaxf(acc[mt][nt][0] + b2v.x, 0.f);
            float m1 = fmaxf(acc[mt][nt][1] + b2v.y, 0.f);
            float m2 = fmaxf(acc[mt][nt][2] + b2v.x, 0.f);
            float m3 = fmaxf(acc[mt][nt][3] + b2v.y, 0.f);
            gp[mt][0] += m0 * wgv.x + m1 * wgv.y;
            gp[mt][1] += m2 * wgv.x + m3 * wgv.y;
            acc[mt][nt][0] = m0; acc[mt][nt][1] = m1;
            acc[mt][nt][2] = m2; acc[mt][nt][3] = m3;
        }
#pragma unroll
        for (int mt = 0; mt < 2; mt++) {
            atomicAdd(&gsm[wm * 32 + mt * 16 + g],     gp[mt][0]);
            atomicAdd(&gsm[wm * 32 + mt * 16 + g + 8], gp[mt][1]);
        }
    }
    __syncthreads();
    if (tid < 64) gsm[tid] = 1.f / (1.f + expf(-(gsm[tid] + __ldg(bg))));
    __syncthreads();

    // ===== scatter: mi[dst] += m * g =====
    {
        float* g_mif = (float*)g_mi4;
#pragma unroll
        for (int mt = 0; mt < 2; mt++) {
            int r = wm * 32 + mt * 16 + g;
            float gg0 = gsm[r], gg1 = gsm[r + 8];
            int d0 = dsts[r], d8 = dsts[r + 8];
#pragma unroll
            for (int nt = 0; nt < 8; nt++) {
                int c = wn * 64 + nt * 8 + q * 2;
                atomicAdd((float2*)&g_mif[d0 * 128 + c],
                          make_float2(acc[mt][nt][0] * gg0, acc[mt][nt][1] * gg0));
                atomicAdd((float2*)&g_mif[d8 * 128 + c],
                          make_float2(acc[mt][nt][2] * gg1, acc[mt][nt][3] * gg1));
            }
        }
    }
}

// ---------------- launch ----------------
extern "C" void kernel_launch(void* const* d_in, const int* in_sizes, int n_in,
                              void* d_out, int out_size)
{
    const float* h   = (const float*)d_in[0];
    const int*   ei  = (const int*)d_in[1];
    const float* ea  = (const float*)d_in[2];
    const float* We1 = (const float*)d_in[3];
    const float* b1  = (const float*)d_in[4];
    const float* We2 = (const float*)d_in[5];
    const float* b2  = (const float*)d_in[6];
    const float* Wg  = (const float*)d_in[7];
    const float* bg  = (const float*)d_in[8];
    const float* Wn1 = (const float*)d_in[9];
    const float* bn1 = (const float*)d_in[10];
    const float* Wn2 = (const float*)d_in[11];
    const float* bn2 = (const float*)d_in[12];
    float* out = (float*)d_out;

    cudaFuncSetAttribute(edge_kernel, cudaFuncAttributeMaxDynamicSharedMemorySize, SMEM_EDGE);
    cudaFuncSetAttribute(pq_tensor_kernel, cudaFuncAttributeMaxDynamicSharedMemorySize, SMEM_PQ);
    cudaFuncSetAttribute(node_tensor_kernel, cudaFuncAttributeMaxDynamicSharedMemorySize, SMEM_NODE);

    const int nblk = (N_NODES + 63) / 64;     // 782
    prep_zero_kernel<<<(N_NODES * (HID / 4) + 511) / 512, 512>>>(We1, We2, Wn1, Wn2);
    pq_tensor_kernel<<<nblk, 128, SMEM_PQ>>>(h, b1);
    edge_kernel<<<N_EDGES / 64, 128, SMEM_EDGE>>>(ei, ea, b2, Wg, bg);
    node_tensor_kernel<<<nblk, 128, SMEM_NODE>>>(h, bn1, bn2, out);
}

// round 17
// speedup vs baseline: 1.2757x; 1.0456x over previous
#include <cuda_runtime.h>
#include <cuda_fp16.h>
#include <cstdint>

#define N_NODES 50000
#define N_EDGES 800000
#define HID 128

typedef unsigned long long ull;

// ---------------- device-global scratch (no allocations allowed) ----------------
__device__ float4 g_mi4[N_NODES * (HID / 4)];
__device__ float g_P[N_NODES * HID];          // h @ We1[24:152] + b1  (bias folded)
__device__ float g_Q[N_NODES * HID];          // h @ We1[152:280]
// B fragments (fp16, single-rounded) packed as uint2 {bh0, bh1}
// COALESCED layout: idx = ((nb*KS + ks)*32 + g*4 + q), nb = n>>3
__device__ uint2 g_w1f2[16 * 2 * 32];         // We1[0:24] (K pad 32), KS=2
__device__ uint2 g_w2f2[16 * 8 * 32];         // We2, KS=8
__device__ uint2 g_wpf2[16 * 8 * 32];         // We1[24:152], KS=8
__device__ uint2 g_wqf2[16 * 8 * 32];         // We1[152:280], KS=8
__device__ uint2 g_wn1f2[16 * 16 * 32];       // Wn1 (K=256), KS=16
__device__ uint2 g_wn2f2[16 * 8 * 32];        // Wn2, KS=8

// ---------------- helpers ----------------
// fp16 hi/lo split of an fp32 pair (A operand): a = hi + lo, |lo| <= 2^-11 |a|
__device__ __forceinline__ void split_pack(float v0, float v1, uint32_t& hi, uint32_t& lo) {
    __half2 h2 = __floats2half2_rn(v0, v1);
    float r0 = v0 - __half2float(h2.x);
    float r1 = v1 - __half2float(h2.y);
    __half2 l2 = __floats2half2_rn(r0, r1);
    hi = *reinterpret_cast<uint32_t*>(&h2);
    lo = *reinterpret_cast<uint32_t*>(&l2);
}
// single fp16 pack (B operand)
__device__ __forceinline__ uint32_t pack_h(float v0, float v1) {
    __half2 h2 = __floats2half2_rn(v0, v1);
    return *reinterpret_cast<uint32_t*>(&h2);
}

__device__ __forceinline__ void mma_f16(float* d, const uint32_t* a, const uint32_t* b) {
    asm volatile("mma.sync.aligned.m16n8k16.row.col.f32.f16.f16.f32 "
        "{%0,%1,%2,%3}, {%4,%5,%6,%7}, {%8,%9}, {%0,%1,%2,%3};"
        : "+f"(d[0]), "+f"(d[1]), "+f"(d[2]), "+f"(d[3])
        : "r"(a[0]), "r"(a[1]), "r"(a[2]), "r"(a[3]), "r"(b[0]), "r"(b[1]));
}

// k8 variant: A = {a0 (rows r, k0..7), a1 (rows r+8)}, B = single reg
__device__ __forceinline__ void mma_f16_k8(float* d, uint32_t a0, uint32_t a1, uint32_t b) {
    asm volatile("mma.sync.aligned.m16n8k8.row.col.f32.f16.f16.f32 "
        "{%0,%1,%2,%3}, {%4,%5}, {%6}, {%0,%1,%2,%3};"
        : "+f"(d[0]), "+f"(d[1]), "+f"(d[2]), "+f"(d[3])
        : "r"(a0), "r"(a1), "r"(b));
}

__device__ __forceinline__ uint2 make_bfrag(const float* W, int n, int ks, int q,
                                            int kmax, int ldw) {
    int kp0 = ks * 8 + q, kp1 = ks * 8 + 4 + q;
    float a0 = (2 * kp0     < kmax) ? W[(2 * kp0)     * ldw + n] : 0.f;
    float a1 = (2 * kp0 + 1 < kmax) ? W[(2 * kp0 + 1) * ldw + n] : 0.f;
    float b0 = (2 * kp1     < kmax) ? W[(2 * kp1)     * ldw + n] : 0.f;
    float b1 = (2 * kp1 + 1 < kmax) ? W[(2 * kp1 + 1) * ldw + n] : 0.f;
    return make_uint2(pack_h(a0, a1), pack_h(b0, b1));
}

// decompose coalesced index li (for given log2(KS)) -> n, ks, q
__device__ __forceinline__ void decomp(int li, int ksbits, int& n, int& ks, int& q) {
    q = li & 3;
    int g = (li >> 2) & 7;
    int r2 = li >> 5;
    ks = r2 & ((1 << ksbits) - 1);
    int nb = r2 >> ksbits;
    n = nb * 8 + g;
}

// ---------------- merged zero + prep kernel ----------------
__global__ void prep_zero_kernel(const float* __restrict__ W1, const float* __restrict__ W2,
                                 const float* __restrict__ Wn1, const float* __restrict__ Wn2) {
    int i = blockIdx.x * blockDim.x + threadIdx.x;
    if (i < N_NODES * (HID / 4))
        g_mi4[i] = make_float4(0.f, 0.f, 0.f, 0.f);
    if (i < 25600) {
        int n, ks, q;
        if (i < 1024) {
            decomp(i, 1, n, ks, q);
            g_w1f2[i] = make_bfrag(W1, n, ks, q, 24, 128);
        } else if (i < 5120) {
            int li = i - 1024; decomp(li, 3, n, ks, q);
            g_w2f2[li] = make_bfrag(W2, n, ks, q, 128, 128);
        } else if (i < 9216) {
            int li = i - 5120; decomp(li, 3, n, ks, q);
            g_wpf2[li] = make_bfrag(W1 + 24 * 128, n, ks, q, 128, 128);
        } else if (i < 13312) {
            int li = i - 9216; decomp(li, 3, n, ks, q);
            g_wqf2[li] = make_bfrag(W1 + 152 * 128, n, ks, q, 128, 128);
        } else if (i < 21504) {
            int li = i - 13312; decomp(li, 4, n, ks, q);
            g_wn1f2[li] = make_bfrag(Wn1, n, ks, q, 256, 128);
        } else {
            int li = i - 21504; decomp(li, 3, n, ks, q);
            g_wn2f2[li] = make_bfrag(Wn2, n, ks, q, 128, 128);
        }
    }
}

// ---------------- A-tile staging: 64 rows x 128 k, 128 threads ----------------
__device__ __forceinline__ void stage_tile64(const float* __restrict__ src, int n0,
                                             uint4* ahi4, uint4* alo4, int tid) {
    const int rb = tid >> 5, g = (tid >> 2) & 7, q = tid & 3;
    const int r = rb * 16 + g;
    const int gn0 = n0 + r, gn8 = gn0 + 8;
    const bool v0 = gn0 < N_NODES, v8 = gn8 < N_NODES;
    const float2* s0 = (const float2*)src + (size_t)gn0 * 64;
    const float2* s8 = (const float2*)src + (size_t)gn8 * 64;
    const float2 z = make_float2(0.f, 0.f);
#pragma unroll
    for (int ks = 0; ks < 8; ks++) {
        int kp = ks * 8 + q;
        float2 a = v0 ? __ldg(&s0[kp])     : z;
        float2 b = v8 ? __ldg(&s8[kp])     : z;
        float2 c = v0 ? __ldg(&s0[kp + 4]) : z;
        float2 d = v8 ? __ldg(&s8[kp + 4]) : z;
        uint32_t h0, l0, h1, l1, h2, l2, h3, l3;
        split_pack(a.x, a.y, h0, l0);
        split_pack(b.x, b.y, h1, l1);
        split_pack(c.x, c.y, h2, l2);
        split_pack(d.x, d.y, h3, l3);
        int idx = ((rb * 8 + ks) * 8 + g) * 4 + q;
        ahi4[idx] = make_uint4(h0, h1, h2, h3);
        alo4[idx] = make_uint4(l0, l1, l2, l3);
    }
}

// ---------------- pq kernel: 64 nodes / 128 threads / 4 CTAs per SM ----------------
#define SMEM_PQ 32768

extern "C" __global__ void __launch_bounds__(128, 4)
pq_tensor_kernel(const float* __restrict__ h, const float* __restrict__ b1) {
    extern __shared__ __align__(16) uint4 smf[];
    uint4* ahi4 = smf;
    uint4* alo4 = smf + 1024;

    const int tid = threadIdx.x;
    const int wid = tid >> 5, lane = tid & 31;
    const int g = lane >> 2, q = lane & 3;
    const int wm = wid & 1, wn = wid >> 1;
    const int wq4 = g * 4 + q;
    const int n0 = blockIdx.x * 64;

    stage_tile64(h, n0, ahi4, alo4, tid);
    __syncthreads();

#pragma unroll
    for (int pass = 0; pass < 2; pass++) {
        const uint2* wf = (pass == 0) ? g_wpf2 : g_wqf2;
        float* outp = (pass == 0) ? g_P : g_Q;

        float acc[2][8][4];
#pragma unroll
        for (int mt = 0; mt < 2; mt++)
#pragma unroll
            for (int nt = 0; nt < 8; nt++)
#pragma unroll
                for (int x = 0; x < 4; x++) acc[mt][nt][x] = 0.f;

#pragma unroll 2
        for (int ks = 0; ks < 8; ks++) {
            uint32_t Ah[2][4], Al[2][4];
#pragma unroll
            for (int mt = 0; mt < 2; mt++) {
                int rb = wm * 2 + mt;
                int idx = ((rb * 8 + ks) * 8 + g) * 4 + q;
                uint4 vh = ahi4[idx];
                Ah[mt][0] = vh.x; Ah[mt][1] = vh.y; Ah[mt][2] = vh.z; Ah[mt][3] = vh.w;
                uint4 vl = alo4[idx];
                Al[mt][0] = vl.x; Al[mt][1] = vl.y; Al[mt][2] = vl.z; Al[mt][3] = vl.w;
            }
#pragma unroll
            for (int nt = 0; nt < 8; nt++) {
                uint2 w = __ldg(&wf[((wn * 8 + nt) * 8 + ks) * 32 + wq4]);
                uint32_t bh[2] = {w.x, w.y};
#pragma unroll
                for (int mt = 0; mt < 2; mt++) {
                    mma_f16(acc[mt][nt], Ah[mt], bh);
                    mma_f16(acc[mt][nt], Al[mt], bh);
                }
            }
        }

#pragma unroll
        for (int mt = 0; mt < 2; mt++) {
            int r = wm * 32 + mt * 16 + g;
            int gn0 = n0 + r, gn8 = gn0 + 8;
            bool v0 = gn0 < N_NODES, v8 = gn8 < N_NODES;
#pragma unroll
            for (int nt = 0; nt < 8; nt++) {
                int c = wn * 64 + nt * 8 + q * 2;
                float2 bv = (pass == 0) ? __ldg((const float2*)&b1[c]) : make_float2(0.f, 0.f);
                if (v0) *(float2*)&outp[gn0 * 128 + c] =
                    make_float2(acc[mt][nt][0] + bv.x, acc[mt][nt][1] + bv.y);
                if (v8) *(float2*)&outp[gn8 * 128 + c] =
                    make_float2(acc[mt][nt][2] + bv.x, acc[mt][nt][3] + bv.y);
            }
        }
    }
}

// ---------------- node kernel: 64 nodes / 128 threads / 4 CTAs per SM ----------------
#define SMEM_NODE 32768

extern "C" __global__ void __launch_bounds__(128, 4)
node_tensor_kernel(const float* __restrict__ h,
                   const float* __restrict__ bn1, const float* __restrict__ bn2,
                   float* __restrict__ out)
{
    extern __shared__ __align__(16) uint4 smf[];
    uint4* ahi4 = smf;
    uint4* alo4 = smf + 1024;

    const int tid = threadIdx.x;
    const int wid = tid >> 5, lane = tid & 31;
    const int g = lane >> 2, q = lane & 3;
    const int wm = wid & 1, wn = wid >> 1;
    const int wq4 = g * 4 + q;
    const int n0 = blockIdx.x * 64;

    float acc[2][8][4];
#pragma unroll
    for (int mt = 0; mt < 2; mt++)
#pragma unroll
        for (int nt = 0; nt < 8; nt++)
#pragma unroll
            for (int x = 0; x < 4; x++) acc[mt][nt][x] = 0.f;

    // ===== phase 1a: mi part (Wn1 ks 0..7) =====
    stage_tile64((const float*)g_mi4, n0, ahi4, alo4, tid);
    __syncthreads();
#pragma unroll 2
    for (int ks = 0; ks < 8; ks++) {
        uint32_t Ah[2][4], Al[2][4];
#pragma unroll
        for (int mt = 0; mt < 2; mt++) {
            int rb = wm * 2 + mt;
            int idx = ((rb * 8 + ks) * 8 + g) * 4 + q;
            uint4 vh = ahi4[idx];
            Ah[mt][0] = vh.x; Ah[mt][1] = vh.y; Ah[mt][2] = vh.z; Ah[mt][3] = vh.w;
            uint4 vl = alo4[idx];
            Al[mt][0] = vl.x; Al[mt][1] = vl.y; Al[mt][2] = vl.z; Al[mt][3] = vl.w;
        }
#pragma unroll
        for (int nt = 0; nt < 8; nt++) {
            uint2 w = __ldg(&g_wn1f2[((wn * 8 + nt) * 16 + ks) * 32 + wq4]);
            uint32_t bh[2] = {w.x, w.y};
#pragma unroll
            for (int mt = 0; mt < 2; mt++) {
                mma_f16(acc[mt][nt], Ah[mt], bh);
                mma_f16(acc[mt][nt], Al[mt], bh);
            }
        }
    }
    __syncthreads();

    // ===== phase 1b: h part (Wn1 ks 8..15) =====
    stage_tile64(h, n0, ahi4, alo4, tid);
    __syncthreads();
#pragma unroll 2
    for (int ks = 0; ks < 8; ks++) {
        uint32_t Ah[2][4], Al[2][4];
#pragma unroll
        for (int mt = 0; mt < 2; mt++) {
            int rb = wm * 2 + mt;
            int idx = ((rb * 8 + ks) * 8 + g) * 4 + q;
            uint4 vh = ahi4[idx];
            Ah[mt][0] = vh.x; Ah[mt][1] = vh.y; Ah[mt][2] = vh.z; Ah[mt][3] = vh.w;
            uint4 vl = alo4[idx];
            Al[mt][0] = vl.x; Al[mt][1] = vl.y; Al[mt][2] = vl.z; Al[mt][3] = vl.w;
        }
#pragma unroll
        for (int nt = 0; nt < 8; nt++) {
            uint2 w = __ldg(&g_wn1f2[((wn * 8 + nt) * 16 + (ks + 8)) * 32 + wq4]);
            uint32_t bh[2] = {w.x, w.y};
#pragma unroll
            for (int mt = 0; mt < 2; mt++) {
                mma_f16(acc[mt][nt], Ah[mt], bh);
                mma_f16(acc[mt][nt], Al[mt], bh);
            }
        }
    }
    __syncthreads();

    // ===== epilogue 1: + bn1, relu, split -> fragment smem =====
#pragma unroll
    for (int mt = 0; mt < 2; mt++) {
#pragma unroll
        for (int j = 0; j < 4; j++) {
            uint32_t hi[4], lo[4];
#pragma unroll
            for (int u = 0; u < 2; u++) {
                int nt = 2 * j + u;
                int c = wn * 64 + nt * 8 + q * 2;
                float2 b1v = __ldg((const float2*)&bn1[c]);
                float t0 = fmaxf(acc[mt][nt][0] + b1v.x, 0.f);
                float t1 = fmaxf(acc[mt][nt][1] + b1v.y, 0.f);
                split_pack(t0, t1, hi[2 * u], lo[2 * u]);
                float t2 = fmaxf(acc[mt][nt][2] + b1v.x, 0.f);
                float t3 = fmaxf(acc[mt][nt][3] + b1v.y, 0.f);
                split_pack(t2, t3, hi[2 * u + 1], lo[2 * u + 1]);
            }
            int K8 = wn * 4 + j;
            int rb = wm * 2 + mt;
            int idx = ((rb * 8 + K8) * 8 + g) * 4 + q;
            ahi4[idx] = make_uint4(hi[0], hi[1], hi[2], hi[3]);
            alo4[idx] = make_uint4(lo[0], lo[1], lo[2], lo[3]);
        }
    }
    __syncthreads();

    // ===== phase 2: @ Wn2 =====
#pragma unroll
    for (int mt = 0; mt < 2; mt++)
#pragma unroll
        for (int nt = 0; nt < 8; nt++)
#pragma unroll
            for (int x = 0; x < 4; x++) acc[mt][nt][x] = 0.f;

#pragma unroll 2
    for (int ks = 0; ks < 8; ks++) {
        uint32_t Ah[2][4], Al[2][4];
#pragma unroll
        for (int mt = 0; mt < 2; mt++) {
            int rb = wm * 2 + mt;
            int idx = ((rb * 8 + ks) * 8 + g) * 4 + q;
            uint4 vh = ahi4[idx];
            Ah[mt][0] = vh.x; Ah[mt][1] = vh.y; Ah[mt][2] = vh.z; Ah[mt][3] = vh.w;
            uint4 vl = alo4[idx];
            Al[mt][0] = vl.x; Al[mt][1] = vl.y; Al[mt][2] = vl.z; Al[mt][3] = vl.w;
        }
#pragma unroll
        for (int nt = 0; nt < 8; nt++) {
            uint2 w = __ldg(&g_wn2f2[((wn * 8 + nt) * 8 + ks) * 32 + wq4]);
            uint32_t bh[2] = {w.x, w.y};
#pragma unroll
            for (int mt = 0; mt < 2; mt++) {
                mma_f16(acc[mt][nt], Ah[mt], bh);
                mma_f16(acc[mt][nt], Al[mt], bh);
            }
        }
    }

    // ===== epilogue 2: + bn2 -> out =====
#pragma unroll
    for (int mt = 0; mt < 2; mt++) {
        int r = wm * 32 + mt * 16 + g;
        int gn0 = n0 + r, gn8 = gn0 + 8;
        bool v0 = gn0 < N_NODES, v8 = gn8 < N_NODES;
#pragma unroll
        for (int nt = 0; nt < 8; nt++) {
            int c = wn * 64 + nt * 8 + q * 2;
            float2 b2v = __ldg((const float2*)&bn2[c]);
            if (v0) *(float2*)&out[gn0 * 128 + c] =
                make_float2(acc[mt][nt][0] + b2v.x, acc[mt][nt][1] + b2v.y);
            if (v8) *(float2*)&out[gn8 * 128 + c] =
                make_float2(acc[mt][nt][2] + b2v.x, acc[mt][nt][3] + b2v.y);
        }
    }
}

// ---------------- edge kernel: 64 edges / 128 threads / 4 warps, 4 CTAs per SM ----------------
// smem: a2hi 16KB @0 (eas 6KB overlay), a2lo 16KB @16384,
//       dsts @32768 (256B), srcs @33024 (256B), gsm2 @33280 (512B) ; total 33792
#define SMEM_EDGE 33792

extern "C" __global__ void __launch_bounds__(128, 4)
edge_kernel(const int* __restrict__ ei, const float* __restrict__ ea,
            const float* __restrict__ b2,
            const float* __restrict__ Wg, const float* __restrict__ bg)
{
    extern __shared__ __align__(16) char sm[];
    uint4* a2hi4 = (uint4*)sm;
    uint4* a2lo4 = (uint4*)(sm + 16384);
    float* eas   = (float*)sm;            // overlay, phase-1 only
    int*   dsts  = (int*)(sm + 32768);
    int*   srcs  = (int*)(sm + 33024);
    float* gsm2  = (float*)(sm + 33280);  // [wn][64] partials; [0..63] final gate

    const int tid = threadIdx.x;
    const int wid = tid >> 5, lane = tid & 31;
    const int g = lane >> 2, q = lane & 3;
    const int wm = wid & 1, wn = wid >> 1;     // 2 m-groups (M64) x 2 n-groups (N128)
    const int wq4 = g * 4 + q;
    const int e0 = blockIdx.x * 64;

    if (tid < 64) {
        dsts[tid] = ei[e0 + tid];
        srcs[tid] = ei[N_EDGES + e0 + tid];
    }
    {
        const float4* ea4 = (const float4*)ea;
        for (int i = tid; i < 64 * 6; i += 128) {
            int e = i / 6, j = i % 6;
            *(float4*)&eas[e * 24 + j * 4] = ea4[(e0 + e) * 6 + j];
        }
    }
    __syncthreads();

    float acc[2][8][4];
#pragma unroll
    for (int mt = 0; mt < 2; mt++)
#pragma unroll
        for (int nt = 0; nt < 8; nt++)
#pragma unroll
            for (int x = 0; x < 4; x++) acc[mt][nt][x] = 0.f;

    // ===== phase 1: ea @ W1a (K=24): ks=0 full k16; ks=1 as k8 (k=24..31 exactly zero) =====
    {
        uint32_t Ah[2][4], Al[2][4];
        // --- ks = 0: k = 0..15 ---
#pragma unroll
        for (int mt = 0; mt < 2; mt++) {
            int r = wm * 32 + mt * 16 + g;
            int k0 = q * 2;
            float2 v0 = *(const float2*)&eas[r * 24 + k0];
            split_pack(v0.x, v0.y, Ah[mt][0], Al[mt][0]);
            float2 v1 = *(const float2*)&eas[(r + 8) * 24 + k0];
            split_pack(v1.x, v1.y, Ah[mt][1], Al[mt][1]);
            float2 v2 = *(const float2*)&eas[r * 24 + k0 + 8];
            split_pack(v2.x, v2.y, Ah[mt][2], Al[mt][2]);
            float2 v3 = *(const float2*)&eas[(r + 8) * 24 + k0 + 8];
            split_pack(v3.x, v3.y, Ah[mt][3], Al[mt][3]);
        }
#pragma unroll
        for (int nt = 0; nt < 8; nt++) {
            uint2 w = __ldg(&g_w1f2[((wn * 8 + nt) * 2 + 0) * 32 + wq4]);
            uint32_t bh[2] = {w.x, w.y};
#pragma unroll
            for (int mt = 0; mt < 2; mt++) {
                mma_f16(acc[mt][nt], Ah[mt], bh);
                mma_f16(acc[mt][nt], Al[mt], bh);
            }
        }
        // --- ks = 1: only k = 16..23 nonzero -> m16n8k8 with fragments 0/1 and b.x ---
#pragma unroll
        for (int mt = 0; mt < 2; mt++) {
            int r = wm * 32 + mt * 16 + g;
            int k0 = 16 + q * 2;
            float2 v0 = *(const float2*)&eas[r * 24 + k0];
            split_pack(v0.x, v0.y, Ah[mt][0], Al[mt][0]);
            float2 v1 = *(const float2*)&eas[(r + 8) * 24 + k0];
            split_pack(v1.x, v1.y, Ah[mt][1], Al[mt][1]);
        }
#pragma unroll
        for (int nt = 0; nt < 8; nt++) {
            uint2 w = __ldg(&g_w1f2[((wn * 8 + nt) * 2 + 1) * 32 + wq4]);
#pragma unroll
            for (int mt = 0; mt < 2; mt++) {
                mma_f16_k8(acc[mt][nt], Ah[mt][0], Ah[mt][1], w.x);
                mma_f16_k8(acc[mt][nt], Al[mt][0], Al[mt][1], w.x);
            }
        }
    }
    __syncthreads();

    // ===== epilogue 1: + (P+b1)[dst] + Q[src], relu, split -> a2 =====
#pragma unroll
    for (int mt = 0; mt < 2; mt++) {
        int r = wm * 32 + mt * 16 + g;
        int d0 = dsts[r], s0 = srcs[r];
        int d8 = dsts[r + 8], s8 = srcs[r + 8];
#pragma unroll
        for (int j = 0; j < 4; j++) {
            uint32_t hi[4], lo[4];
#pragma unroll
            for (int u = 0; u < 2; u++) {
                int nt = 2 * j + u;
                int c = wn * 64 + nt * 8 + q * 2;
                float2 pv0 = __ldg((const float2*)&g_P[d0 * 128 + c]);
                float2 qv0 = __ldg((const float2*)&g_Q[s0 * 128 + c]);
                float t0 = fmaxf(acc[mt][nt][0] + pv0.x + qv0.x, 0.f);
                float t1 = fmaxf(acc[mt][nt][1] + pv0.y + qv0.y, 0.f);
                split_pack(t0, t1, hi[2 * u], lo[2 * u]);
                float2 pv8 = __ldg((const float2*)&g_P[d8 * 128 + c]);
                float2 qv8 = __ldg((const float2*)&g_Q[s8 * 128 + c]);
                float t2 = fmaxf(acc[mt][nt][2] + pv8.x + qv8.x, 0.f);
                float t3 = fmaxf(acc[mt][nt][3] + pv8.y + qv8.y, 0.f);
                split_pack(t2, t3, hi[2 * u + 1], lo[2 * u + 1]);
            }
            int K8 = wn * 4 + j;
            int rb = wm * 2 + mt;               // row block 0..3 over M64
            int idx = ((rb * 8 + K8) * 8 + g) * 4 + q;
            a2hi4[idx] = make_uint4(hi[0], hi[1], hi[2], hi[3]);
            a2lo4[idx] = make_uint4(lo[0], lo[1], lo[2], lo[3]);
        }
    }
    __syncthreads();

    // ===== phase 2: layer2 =====
#pragma unroll
    for (int mt = 0; mt < 2; mt++)
#pragma unroll
        for (int nt = 0; nt < 8; nt++)
#pragma unroll
            for (int x = 0; x < 4; x++) acc[mt][nt][x] = 0.f;

#pragma unroll 2
    for (int ks = 0; ks < 8; ks++) {
        uint32_t Ah[2][4], Al[2][4];
#pragma unroll
        for (int mt = 0; mt < 2; mt++) {
            int rb = wm * 2 + mt;
            int idx = ((rb * 8 + ks) * 8 + g) * 4 + q;
            uint4 vh = a2hi4[idx];
            Ah[mt][0] = vh.x; Ah[mt][1] = vh.y; Ah[mt][2] = vh.z; Ah[mt][3] = vh.w;
            uint4 vl = a2lo4[idx];
            Al[mt][0] = vl.x; Al[mt][1] = vl.y; Al[mt][2] = vl.z; Al[mt][3] = vl.w;
        }
#pragma unroll
        for (int nt = 0; nt < 8; nt++) {
            uint2 w = __ldg(&g_w2f2[((wn * 8 + nt) * 8 + ks) * 32 + wq4]);
            uint32_t bh[2] = {w.x, w.y};
#pragma unroll
            for (int mt = 0; mt < 2; mt++) {
                mma_f16(acc[mt][nt], Ah[mt], bh);
                mma_f16(acc[mt][nt], Al[mt], bh);
            }
        }
    }

    // ===== epilogue 2: bias + relu -> m (regs); gate partials via shfl (no atomics) =====
    {
#pragma unroll
        for (int mt = 0; mt < 2; mt++) {
            float s0 = 0.f, s1 = 0.f;
#pragma unroll
            for (int nt = 0; nt < 8; nt++) {
                int c = wn * 64 + nt * 8 + q * 2;
                float2 b2v = __ldg((const float2*)&b2[c]);
                float2 wgv = __ldg((const float2*)&Wg[c]);
                float m0 = fmaxf(acc[mt][nt][0] + b2v.x, 0.f);
                float m1 = fmaxf(acc[mt][nt][1] + b2v.y, 0.f);
                float m2 = fmaxf(acc[mt][nt][2] + b2v.x, 0.f);
                float m3 = fmaxf(acc[mt][nt][3] + b2v.y, 0.f);
                s0 += m0 * wgv.x + m1 * wgv.y;
                s1 += m2 * wgv.x + m3 * wgv.y;
                acc[mt][nt][0] = m0; acc[mt][nt][1] = m1;
                acc[mt][nt][2] = m2; acc[mt][nt][3] = m3;
            }
            // reduce over the 4 q-lanes (adjacent lane ids)
            s0 += __shfl_xor_sync(0xffffffffu, s0, 1);
            s0 += __shfl_xor_sync(0xffffffffu, s0, 2);
            s1 += __shfl_xor_sync(0xffffffffu, s1, 1);
            s1 += __shfl_xor_sync(0xffffffffu, s1, 2);
            if (q == 0) {
                int r = wm * 32 + mt * 16 + g;
                gsm2[wn * 64 + r]     = s0;
                gsm2[wn * 64 + r + 8] = s1;
            }
        }
    }
    __syncthreads();
    if (tid < 64) {
        float tot = gsm2[tid] + gsm2[64 + tid];
        gsm2[tid] = 1.f / (1.f + expf(-(tot + __ldg(bg))));
    }
    __syncthreads();

    // ===== scatter: mi[dst] += m * g =====
    {
        float* g_mif = (float*)g_mi4;
#pragma unroll
        for (int mt = 0; mt < 2; mt++) {
            int r = wm * 32 + mt * 16 + g;
            float gg0 = gsm2[r], gg1 = gsm2[r + 8];
            int d0 = dsts[r], d8 = dsts[r + 8];
#pragma unroll
            for (int nt = 0; nt < 8; nt++) {
                int c = wn * 64 + nt * 8 + q * 2;
                atomicAdd((float2*)&g_mif[d0 * 128 + c],
                          make_float2(acc[mt][nt][0] * gg0, acc[mt][nt][1] * gg0));
                atomicAdd((float2*)&g_mif[d8 * 128 + c],
                          make_float2(acc[mt][nt][2] * gg1, acc[mt][nt][3] * gg1));
            }
        }
    }
}

// ---------------- launch ----------------
extern "C" void kernel_launch(void* const* d_in, const int* in_sizes, int n_in,
                              void* d_out, int out_size)
{
    const float* h   = (const float*)d_in[0];
    const int*   ei  = (const int*)d_in[1];
    const float* ea  = (const float*)d_in[2];
    const float* We1 = (const float*)d_in[3];
    const float* b1  = (const float*)d_in[4];
    const float* We2 = (const float*)d_in[5];
    const float* b2  = (const float*)d_in[6];
    const float* Wg  = (const float*)d_in[7];
    const float* bg  = (const float*)d_in[8];
    const float* Wn1 = (const float*)d_in[9];
    const float* bn1 = (const float*)d_in[10];
    const float* Wn2 = (const float*)d_in[11];
    const float* bn2 = (const float*)d_in[12];
    float* out = (float*)d_out;

    cudaFuncSetAttribute(edge_kernel, cudaFuncAttributeMaxDynamicSharedMemorySize, SMEM_EDGE);
    cudaFuncSetAttribute(pq_tensor_kernel, cudaFuncAttributeMaxDynamicSharedMemorySize, SMEM_PQ);
    cudaFuncSetAttribute(node_tensor_kernel, cudaFuncAttributeMaxDynamicSharedMemorySize, SMEM_NODE);

    const int nblk = (N_NODES + 63) / 64;     // 782
    prep_zero_kernel<<<(N_NODES * (HID / 4) + 511) / 512, 512>>>(We1, We2, Wn1, Wn2);
    pq_tensor_kernel<<<nblk, 128, SMEM_PQ>>>(h, b1);
    edge_kernel<<<N_EDGES / 64, 128, SMEM_EDGE>>>(ei, ea, b2, Wg, bg);
    node_tensor_kernel<<<nblk, 128, SMEM_NODE>>>(h, bn1, bn2, out);
}